// round 13
// baseline (speedup 1.0000x reference)
#include <cuda_runtime.h>
#include <cuda_bf16.h>
#include <math.h>
#include <stdint.h>

#define SLOPE 0.2f

// ---------------- static scratch (no cudaMalloc allowed) ----------------
#define NMAX 200000
#define SEGMAX 1360000
#define EVMAX  5300000
#define MROWS  1360000            // total m rows across a batched gemm phase

__device__ __align__(16) float g_m[(size_t)MROWS * 64];     // per-gemm m regions
__device__ float g_d[(size_t)2 * MROWS + 16];               // per-gemm d1/d2 regions
__device__ __align__(16) float g_x0l[(size_t)100000 * 64];
__device__ __align__(16) float g_x1l[(size_t)200000 * 64];
__device__ __align__(16) float g_x2l[(size_t)150000 * 64];
__device__ __align__(16) float g_x3l[(size_t)50000 * 64];

__device__ int g_cnt[SEGMAX + 8];
__device__ int g_offs[SEGMAX + 8];
__device__ int g_cur[SEGMAX + 8];
__device__ int g_val[EVMAX];
__device__ float g_w[EVMAX];        // unnormalized exp weights (global CSR pos)
__device__ float g_inv[SEGMAX + 8]; // per-segment 1/sum (global segment index)
__device__ int g_bsum[4096];

// ---------------- batch descriptors (passed by value) ----------------
struct GemmTask { const float* x; const float* W; const float* a;
                  float* m; float* d1; float* d2; int n; };
struct GemmBatch { GemmTask t[10]; int blk_end[10]; };

struct SegwTask { const int* offs; const float* dS; const float* dO;
                  float* inv; int nseg; };
struct SegwBatch { SegwTask t[8]; int blk_end[8]; };

// fused gather: up to two CSR lists per output; single pure store.
struct Gat2Task { const int* offs1; const float* inv1; const float4* m1;
                  const int* offs2; const float* inv2; const float4* m2;
                  float* out; int nseg; };
struct Gat2Batch { Gat2Task t[4]; int blk_end[4]; };

struct ListBatch { const int* seg[10]; const int* oth[10];
                   int base[10]; int E[10]; int blk_end[10]; };

// ---------------- mma.sync bf16 GEMM (baseline PTX, works on sm_103) ------
// m = x @ W, split precision: x=xh+xl, W=Wh+Wl (bf16);
// D = xh@Wh + xh@Wl + xl@Wh in fp32.
// A staged in smem as PRE-PACKED bf16 hi/lo (padded stride 72, no swizzle:
// fragment LDS banks = 4g+tig, conflict-free). B^T hi/lo likewise.
// Dynamic smem ~56KB, 3 CTAs/SM.
#define AST 72
#define EL_AH 0
#define EL_AL (128 * AST)
#define EL_BH (2 * 128 * AST)
#define EL_BL (2 * 128 * AST + 64 * AST)
#define EL_END (2 * 128 * AST + 2 * 64 * AST)
#define GSMEM_BYTES (EL_END * 2 + 512)

__device__ __forceinline__ void mma16816(float* d, const uint32_t* a,
                                         uint32_t b0, uint32_t b1) {
    asm("mma.sync.aligned.m16n8k16.row.col.f32.bf16.bf16.f32 "
        "{%0,%1,%2,%3}, {%4,%5,%6,%7}, {%8,%9}, {%0,%1,%2,%3};"
        : "+f"(d[0]), "+f"(d[1]), "+f"(d[2]), "+f"(d[3])
        : "r"(a[0]), "r"(a[1]), "r"(a[2]), "r"(a[3]), "r"(b0), "r"(b1));
}

__device__ __forceinline__ uint32_t pack_hi2(float fx, float fy) {
    __nv_bfloat162 h = __halves2bfloat162(__float2bfloat16(fx), __float2bfloat16(fy));
    return *(uint32_t*)&h;
}
__device__ __forceinline__ uint32_t pack_lo2(float fx, float fy) {
    float rx = fx - __bfloat162float(__float2bfloat16(fx));
    float ry = fy - __bfloat162float(__float2bfloat16(fy));
    __nv_bfloat162 h = __halves2bfloat162(__float2bfloat16(rx), __float2bfloat16(ry));
    return *(uint32_t*)&h;
}

__global__ void __launch_bounds__(256, 3) k_gemm_batch(GemmBatch bat)
{
    extern __shared__ char dsm[];
    __nv_bfloat16* sb = (__nv_bfloat16*)dsm;
    float* as_ = (float*)(sb + EL_END);

    int id = 0;
    while ((int)blockIdx.x >= bat.blk_end[id]) id++;
    int bstart = id ? bat.blk_end[id - 1] : 0;
    const float* __restrict__ x = bat.t[id].x;
    const float* __restrict__ W = bat.t[id].W;
    float* __restrict__ m  = bat.t[id].m;
    float* __restrict__ d1 = bat.t[id].d1;
    float* __restrict__ d2 = bat.t[id].d2;
    int n = bat.t[id].n;

    int tid = threadIdx.x;
    int w = tid >> 5, lane = tid & 31;
    int g = lane >> 2, tig = lane & 3;
    int row0 = ((int)blockIdx.x - bstart) * 128;

    // stage A tile: coalesced float4 LDG -> packed bf16 hi/lo, stride AST
    for (int i = tid; i < 2048; i += 256) {
        int r = i >> 4, cg = i & 15;
        float4 v = make_float4(0.f, 0.f, 0.f, 0.f);
        int gr = row0 + r;
        if (gr < n) v = *(const float4*)&x[(size_t)gr * 64 + cg * 4];
        uint32_t h01 = pack_hi2(v.x, v.y);
        uint32_t h23 = pack_hi2(v.z, v.w);
        uint32_t l01 = pack_lo2(v.x, v.y);
        uint32_t l23 = pack_lo2(v.z, v.w);
        int el = r * AST + cg * 4;
        *(uint2*)&sb[EL_AH + el] = make_uint2(h01, h23);
        *(uint2*)&sb[EL_AL + el] = make_uint2(l01, l23);
    }
    // stage W^T hi/lo: sb[EL_BH + c*AST + k] = bf16(W[k][c])
    for (int i = tid; i < 4096; i += 256) {
        int k = i >> 6, c = i & 63;
        float v = W[i];
        __nv_bfloat16 h = __float2bfloat16(v);
        sb[EL_BH + c * AST + k] = h;
        sb[EL_BL + c * AST + k] = __float2bfloat16(v - __bfloat162float(h));
    }
    if (tid < 128) as_[tid] = bat.t[id].a[tid];
    __syncthreads();

    float D[8][4];
#pragma unroll
    for (int nt = 0; nt < 8; nt++)
#pragma unroll
        for (int j = 0; j < 4; j++) D[nt][j] = 0.f;

    int rloc = w * 16 + g;           // local row of fragment row a0/a2
#pragma unroll
    for (int ks = 0; ks < 4; ks++) {
        int ab = rloc * AST + ks * 16 + tig * 2;
        uint32_t ah[4], al[4];
        ah[0] = *(uint32_t*)&sb[EL_AH + ab];
        ah[1] = *(uint32_t*)&sb[EL_AH + ab + 8 * AST];
        ah[2] = *(uint32_t*)&sb[EL_AH + ab + 8];
        ah[3] = *(uint32_t*)&sb[EL_AH + ab + 8 * AST + 8];
        al[0] = *(uint32_t*)&sb[EL_AL + ab];
        al[1] = *(uint32_t*)&sb[EL_AL + ab + 8 * AST];
        al[2] = *(uint32_t*)&sb[EL_AL + ab + 8];
        al[3] = *(uint32_t*)&sb[EL_AL + ab + 8 * AST + 8];
#pragma unroll
        for (int nt = 0; nt < 8; nt++) {
            int bb = (nt * 8 + g) * AST + ks * 16 + tig * 2;
            uint32_t bh0 = *(uint32_t*)&sb[EL_BH + bb];
            uint32_t bh1 = *(uint32_t*)&sb[EL_BH + bb + 8];
            uint32_t bl0 = *(uint32_t*)&sb[EL_BL + bb];
            uint32_t bl1 = *(uint32_t*)&sb[EL_BL + bb + 8];
            mma16816(D[nt], ah, bh0, bh1);
            mma16816(D[nt], ah, bl0, bl1);
            mma16816(D[nt], al, bh0, bh1);
        }
    }

    int r0 = row0 + rloc;
    int r1 = r0 + 8;
    bool v0 = r0 < n, v1 = r1 < n;
    float s1a = 0.f, s2a = 0.f, s1b = 0.f, s2b = 0.f;
#pragma unroll
    for (int nt = 0; nt < 8; nt++) {
        int c0 = nt * 8 + tig * 2;
        float2 a1p = *(float2*)&as_[c0];
        float2 a2p = *(float2*)&as_[64 + c0];
        s1a = fmaf(D[nt][0], a1p.x, fmaf(D[nt][1], a1p.y, s1a));
        s2a = fmaf(D[nt][0], a2p.x, fmaf(D[nt][1], a2p.y, s2a));
        s1b = fmaf(D[nt][2], a1p.x, fmaf(D[nt][3], a1p.y, s1b));
        s2b = fmaf(D[nt][2], a2p.x, fmaf(D[nt][3], a2p.y, s2b));
        if (v0)
            *(float2*)&m[(size_t)r0 * 64 + c0] = make_float2(D[nt][0], D[nt][1]);
        if (v1)
            *(float2*)&m[(size_t)r1 * 64 + c0] = make_float2(D[nt][2], D[nt][3]);
    }
#pragma unroll
    for (int off = 1; off < 4; off <<= 1) {
        s1a += __shfl_xor_sync(0xFFFFFFFFu, s1a, off);
        s2a += __shfl_xor_sync(0xFFFFFFFFu, s2a, off);
        s1b += __shfl_xor_sync(0xFFFFFFFFu, s1b, off);
        s2b += __shfl_xor_sync(0xFFFFFFFFu, s2b, off);
    }
    if (tig == 0) {
        if (v0) { d1[r0] = s1a; d2[r0] = s2a; }
        if (v1) { d1[r1] = s1b; d2[r1] = s2b; }
    }
}

// ---------------- CSR build (batched) ----------------
__global__ void k_hist_batch(ListBatch bat, int* __restrict__ cnt)
{
    int id = 0;
    while ((int)blockIdx.x >= bat.blk_end[id]) id++;
    int bstart = id ? bat.blk_end[id - 1] : 0;
    int e = ((int)blockIdx.x - bstart) * 256 + threadIdx.x;
    if (e >= bat.E[id]) return;
    atomicAdd(&cnt[bat.base[id] + bat.seg[id][e]], 1);
}

__global__ void k_scatter_batch(ListBatch bat, int* __restrict__ cur,
                                int* __restrict__ val)
{
    int id = 0;
    while ((int)blockIdx.x >= bat.blk_end[id]) id++;
    int bstart = id ? bat.blk_end[id - 1] : 0;
    int e = ((int)blockIdx.x - bstart) * 256 + threadIdx.x;
    if (e >= bat.E[id]) return;
    int pos = atomicAdd(&cur[bat.base[id] + bat.seg[id][e]], 1);
    val[pos] = bat.oth[id][e];
}

__global__ void k_scan1(const int* __restrict__ in, int* __restrict__ out,
                        int* __restrict__ bsum, int n)
{
    __shared__ int ts[256];
    int tid = threadIdx.x;
    int base = blockIdx.x * 1024 + tid * 4;
    int v[4]; int s = 0;
#pragma unroll
    for (int i = 0; i < 4; i++) {
        int idx = base + i;
        v[i] = (idx < n) ? in[idx] : 0;
        s += v[i];
    }
    ts[tid] = s; __syncthreads();
    for (int off = 1; off < 256; off <<= 1) {
        int t = (tid >= off) ? ts[tid - off] : 0;
        __syncthreads();
        ts[tid] += t;
        __syncthreads();
    }
    int excl = ts[tid] - s;
    if (tid == 255) bsum[blockIdx.x] = ts[255];
    int run = excl;
#pragma unroll
    for (int i = 0; i < 4; i++) {
        int idx = base + i;
        if (idx < n) out[idx] = run;
        run += v[i];
    }
}

__global__ void k_scan2(int* __restrict__ bsum, int nb)
{
    __shared__ int ts[256];
    __shared__ int carry;
    int tid = threadIdx.x;
    if (tid == 0) carry = 0;
    __syncthreads();
    for (int c0 = 0; c0 < nb; c0 += 256) {
        int i = c0 + tid;
        int v = (i < nb) ? bsum[i] : 0;
        ts[tid] = v; __syncthreads();
        for (int off = 1; off < 256; off <<= 1) {
            int t = (tid >= off) ? ts[tid - off] : 0;
            __syncthreads();
            ts[tid] += t;
            __syncthreads();
        }
        int excl = ts[tid] - v + carry;
        __syncthreads();
        if (i < nb) bsum[i] = excl;
        if (tid == 255) carry = excl + v;
        __syncthreads();
    }
}

__global__ void k_scan3(int* __restrict__ out, const int* __restrict__ bsum, int n)
{
    int i = blockIdx.x * blockDim.x + threadIdx.x;
    if (i < n) out[i] += bsum[i >> 10];
}

// ---------------- per-segment softmax weights (batched) ----------------
__global__ void k_segw_batch(SegwBatch bat, const int* __restrict__ val,
                             float* __restrict__ w)
{
    int id = 0;
    while ((int)blockIdx.x >= bat.blk_end[id]) id++;
    int bstart = id ? bat.blk_end[id - 1] : 0;
    int s = ((int)blockIdx.x - bstart) * 256 + threadIdx.x;
    if (s >= bat.t[id].nseg) return;
    const int* offs = bat.t[id].offs;
    int p0 = offs[s], p1 = offs[s + 1];
    if (p0 == p1) return;
    float ds = bat.t[id].dS[s];
    const float* dO = bat.t[id].dO;
    float sum = 0.f;
    for (int p = p0; p < p1; p++) {
        int o = __ldg(&val[p]);
        float v = ds + __ldg(&dO[o]);
        v = (v > 0.f) ? v : SLOPE * v;
        float e = __expf(fminf(v, 80.f));
        w[p] = e;
        sum += e;
    }
    bat.t[id].inv[s] = 1.f / sum;
}

// ---------------- fused gather aggregation (batched) ----------------
__global__ void k_gat2_batch(Gat2Batch bat, const int* __restrict__ val,
                             const float* __restrict__ w)
{
    int id = 0;
    while ((int)blockIdx.x >= bat.blk_end[id]) id++;
    int bstart = id ? bat.blk_end[id - 1] : 0;
    int t = ((int)blockIdx.x - bstart) * 256 + threadIdx.x;
    int s = t >> 3;
    if (s >= bat.t[id].nseg) return;
    int g = t & 7;
    const Gat2Task& tk = bat.t[id];

    float4 A = make_float4(0.f, 0.f, 0.f, 0.f);
    float4 B = make_float4(0.f, 0.f, 0.f, 0.f);

#pragma unroll 1
    for (int li = 0; li < 2; li++) {
        const int* offs = li ? tk.offs2 : tk.offs1;
        if (!offs) break;
        const float* invp = li ? tk.inv2 : tk.inv1;
        const float4* m = li ? tk.m2 : tk.m1;
        int p0 = offs[s], p1 = offs[s + 1];
        if (p0 == p1) continue;

        float4 LA = make_float4(0.f, 0.f, 0.f, 0.f);
        float4 LB = make_float4(0.f, 0.f, 0.f, 0.f);
        int p = p0;
        for (; p + 2 <= p1; p += 2) {
            float w0 = __ldg(&w[p]);
            float w1 = __ldg(&w[p + 1]);
            int o0 = __ldg(&val[p]);
            int o1 = __ldg(&val[p + 1]);
            float4 a0 = __ldg(&m[o0 * 16 + g * 2]);
            float4 a1 = __ldg(&m[o0 * 16 + g * 2 + 1]);
            float4 b0 = __ldg(&m[o1 * 16 + g * 2]);
            float4 b1 = __ldg(&m[o1 * 16 + g * 2 + 1]);
            LA.x = fmaf(w0, a0.x, LA.x); LA.y = fmaf(w0, a0.y, LA.y);
            LA.z = fmaf(w0, a0.z, LA.z); LA.w = fmaf(w0, a0.w, LA.w);
            LB.x = fmaf(w0, a1.x, LB.x); LB.y = fmaf(w0, a1.y, LB.y);
            LB.z = fmaf(w0, a1.z, LB.z); LB.w = fmaf(w0, a1.w, LB.w);
            LA.x = fmaf(w1, b0.x, LA.x); LA.y = fmaf(w1, b0.y, LA.y);
            LA.z = fmaf(w1, b0.z, LA.z); LA.w = fmaf(w1, b0.w, LA.w);
            LB.x = fmaf(w1, b1.x, LB.x); LB.y = fmaf(w1, b1.y, LB.y);
            LB.z = fmaf(w1, b1.z, LB.z); LB.w = fmaf(w1, b1.w, LB.w);
        }
        if (p < p1) {
            float w0 = __ldg(&w[p]);
            int o0 = __ldg(&val[p]);
            float4 a0 = __ldg(&m[o0 * 16 + g * 2]);
            float4 a1 = __ldg(&m[o0 * 16 + g * 2 + 1]);
            LA.x = fmaf(w0, a0.x, LA.x); LA.y = fmaf(w0, a0.y, LA.y);
            LA.z = fmaf(w0, a0.z, LA.z); LA.w = fmaf(w0, a0.w, LA.w);
            LB.x = fmaf(w0, a1.x, LB.x); LB.y = fmaf(w0, a1.y, LB.y);
            LB.z = fmaf(w0, a1.z, LB.z); LB.w = fmaf(w0, a1.w, LB.w);
        }
        float iv = __ldg(&invp[s]);
        A.x = fmaf(LA.x, iv, A.x); A.y = fmaf(LA.y, iv, A.y);
        A.z = fmaf(LA.z, iv, A.z); A.w = fmaf(LA.w, iv, A.w);
        B.x = fmaf(LB.x, iv, B.x); B.y = fmaf(LB.y, iv, B.y);
        B.z = fmaf(LB.z, iv, B.z); B.w = fmaf(LB.w, iv, B.w);
    }

    float4* dst = (float4*)&tk.out[(size_t)s * 64 + g * 8];
    dst[0] = A;
    dst[1] = B;
}

extern "C" void kernel_launch(void* const* d_in, const int* in_sizes, int n_in,
                              void* d_out, int out_size)
{
    cudaFuncSetAttribute(k_gemm_batch, cudaFuncAttributeMaxDynamicSharedMemorySize,
                         GSMEM_BYTES);

    const float* x0   = (const float*)d_in[0];
    const float* x1   = (const float*)d_in[1];
    const float* x2   = (const float*)d_in[2];
    const float* x3   = (const float*)d_in[3];
    const float* hbsW = (const float*)d_in[4];
    const float* hbsA = (const float*)d_in[5];
    const float* hWs  = (const float*)d_in[6];
    const float* hWt  = (const float*)d_in[7];
    const float* hA   = (const float*)d_in[8];
    const int* a0r = (const int*)d_in[9];
    const int* a0c = (const int*)d_in[10];
    const int* a1r = (const int*)d_in[11];
    const int* a1c = (const int*)d_in[12];
    const int* a2r = (const int*)d_in[13];
    const int* a2c = (const int*)d_in[14];
    const int* c3r = (const int*)d_in[15];
    const int* c3c = (const int*)d_in[16];
    const int* i1r = (const int*)d_in[17];
    const int* i1c = (const int*)d_in[18];
    const int* i2r = (const int*)d_in[19];
    const int* i2c = (const int*)d_in[20];
    const int* i3r = (const int*)d_in[21];
    const int* i3c = (const int*)d_in[22];

    int n0 = in_sizes[0] / 64, n1 = in_sizes[1] / 64;
    int n2 = in_sizes[2] / 64, n3 = in_sizes[3] / 64;
    int Ea0 = in_sizes[9],  Ea1 = in_sizes[11], Ea2 = in_sizes[13];
    int Ec3 = in_sizes[15], Ei1 = in_sizes[17], Ei2 = in_sizes[19], Ei3 = in_sizes[21];

    float *mbuf, *dbuf, *x0l, *x1l, *x2l, *x3l, *w, *inv;
    int *cnt, *offs, *cur, *val, *bsum;
    cudaGetSymbolAddress((void**)&mbuf, g_m);
    cudaGetSymbolAddress((void**)&dbuf, g_d);
    cudaGetSymbolAddress((void**)&x0l, g_x0l);
    cudaGetSymbolAddress((void**)&x1l, g_x1l);
    cudaGetSymbolAddress((void**)&x2l, g_x2l);
    cudaGetSymbolAddress((void**)&x3l, g_x3l);
    cudaGetSymbolAddress((void**)&cnt,  g_cnt);
    cudaGetSymbolAddress((void**)&offs, g_offs);
    cudaGetSymbolAddress((void**)&cur,  g_cur);
    cudaGetSymbolAddress((void**)&val,  g_val);
    cudaGetSymbolAddress((void**)&w,    g_w);
    cudaGetSymbolAddress((void**)&inv,  g_inv);
    cudaGetSymbolAddress((void**)&bsum, g_bsum);

    float* out0 = (float*)d_out;
    float* out1 = out0 + (size_t)n0 * 64;
    float* out2 = out1 + (size_t)n1 * 64;
    float* out3 = out2 + (size_t)n2 * 64;

    // ------- CSR bases -------
    int b0 = 0;
    int b1 = b0 + n0;
    int b2 = b1 + n1;
    int b3 = b2 + n2;
    int b4 = b3 + n3;
    int b5 = b4 + n0;
    int b6 = b5 + n1;
    int b7 = b6 + n1;
    int b8 = b7 + n2;
    int b9 = b8 + n2;
    int segtot = b9 + n3;
    int nscan = segtot + 1;

    // ------- list batch (10 edge lists) -------
    ListBatch lb{};
    const int* segA[10] = {a0r, a1r, a2r, c3r, i1r, i1c, i2r, i2c, i3r, i3c};
    const int* othA[10] = {a0c, a1c, a2c, c3c, i1c, i1r, i2c, i2r, i3c, i3r};
    int baseA[10] = {b0, b1, b2, b3, b4, b5, b6, b7, b8, b9};
    int EA[10] = {Ea0, Ea1, Ea2, Ec3, Ei1, Ei1, Ei2, Ei2, Ei3, Ei3};
    {
        int acc = 0;
        for (int i = 0; i < 10; i++) {
            lb.seg[i] = segA[i]; lb.oth[i] = othA[i];
            lb.base[i] = baseA[i]; lb.E[i] = EA[i];
            acc += (EA[i] + 255) / 256;
            lb.blk_end[i] = acc;
        }
    }
    int list_blocks = lb.blk_end[9];

    // ------- GEMM batches -------
    const float* L1x[7] = {x0, x1, x0, x2, x1, x3, x2};
    const float* L1W[7] = {hbsW, hWs, hWt, hWs + 4096, hWt + 4096, hWs + 2 * 4096, hWt + 2 * 4096};
    const float* L1a[7] = {hbsA, hA, hA, hA + 128, hA + 128, hA + 2 * 128, hA + 2 * 128};
    int L1n[7] = {n0, n1, n0, n2, n1, n3, n2};
    GemmBatch gb1{};
    float* L1m[7]; float* L1d1[7]; float* L1d2[7];
    {
        size_t moff = 0; size_t doff = 0; int acc = 0;
        for (int i = 0; i < 7; i++) {
            L1m[i] = mbuf + moff * 64; moff += (size_t)L1n[i];
            L1d1[i] = dbuf + doff; L1d2[i] = dbuf + doff + L1n[i];
            doff += (size_t)2 * L1n[i];
            gb1.t[i] = GemmTask{L1x[i], L1W[i], L1a[i], L1m[i], L1d1[i], L1d2[i], L1n[i]};
            acc += (L1n[i] + 127) / 128;
            gb1.blk_end[i] = acc;
        }
        for (int i = 7; i < 10; i++) gb1.blk_end[i] = acc + 1 + i;
    }
    int gemm1_blocks = gb1.blk_end[6];

    const float* L2x[10] = {x0l, x1l, x2l, x3l, x1l, x0l, x2l, x1l, x3l, x2l};
    const float* L2W[10] = {hbsW + 4096, hbsW + 2 * 4096, hbsW + 3 * 4096, hbsW + 4 * 4096,
                            hWs + 3 * 4096, hWt + 3 * 4096, hWs + 4 * 4096, hWt + 4 * 4096,
                            hWs + 5 * 4096, hWt + 5 * 4096};
    const float* L2a[10] = {hbsA + 128, hbsA + 2 * 128, hbsA + 3 * 128, hbsA + 4 * 128,
                            hA + 3 * 128, hA + 3 * 128, hA + 4 * 128, hA + 4 * 128,
                            hA + 5 * 128, hA + 5 * 128};
    int L2n[10] = {n0, n1, n2, n3, n1, n0, n2, n1, n3, n2};
    GemmBatch gb2{};
    float* L2m[10]; float* L2d1[10]; float* L2d2[10];
    {
        size_t moff = 0; size_t doff = 0; int acc = 0;
        for (int i = 0; i < 10; i++) {
            L2m[i] = mbuf + moff * 64; moff += (size_t)L2n[i];
            L2d1[i] = dbuf + doff; L2d2[i] = dbuf + doff + L2n[i];
            doff += (size_t)2 * L2n[i];
            gb2.t[i] = GemmTask{L2x[i], L2W[i], L2a[i], L2m[i], L2d1[i], L2d2[i], L2n[i]};
            acc += (L2n[i] + 127) / 128;
            gb2.blk_end[i] = acc;
        }
    }
    int gemm2_blocks = gb2.blk_end[9];

    // ------- seg_w batches -------
    auto mk_segw = [&](SegwBatch& sb, int ntask,
                       const int* bases, const float** dS, const float** dO,
                       const int* nsegs) {
        int acc = 0;
        for (int i = 0; i < ntask; i++) {
            sb.t[i] = SegwTask{offs + bases[i], dS[i], dO[i], inv + bases[i], nsegs[i]};
            acc += (nsegs[i] + 255) / 256;
            sb.blk_end[i] = acc;
        }
        for (int i = ntask; i < 8; i++) sb.blk_end[i] = acc + 1 + i;
        return acc;
    };

    SegwBatch sw1{};
    {
        int bases[7]  = {b0, b4, b5, b6, b7, b8, b9};
        const float* dS[7] = {L1d1[0], L1d2[2], L1d2[1], L1d2[4], L1d2[3], L1d2[6], L1d2[5]};
        const float* dO[7] = {L1d2[0], L1d1[1], L1d1[2], L1d1[3], L1d1[4], L1d1[5], L1d1[6]};
        int nsegs[7] = {n0, n0, n1, n1, n2, n2, n3};
        mk_segw(sw1, 7, bases, dS, dO, nsegs);
    }
    int sw1_blocks = sw1.blk_end[6];

    SegwBatch sw2{};
    {
        int bases[7]  = {b0, b1, b2, b3, b5, b7, b9};
        const float* dS[7] = {L2d1[0], L2d1[1], L2d1[2], L2d1[3], L2d2[4], L2d2[6], L2d2[8]};
        const float* dO[7] = {L2d2[0], L2d2[1], L2d2[2], L2d2[3], L2d1[5], L2d1[7], L2d1[9]};
        int nsegs[7] = {n0, n1, n2, n3, n1, n2, n3};
        mk_segw(sw2, 7, bases, dS, dO, nsegs);
    }
    int sw2_blocks = sw2.blk_end[6];

    // ------- fused gat batches -------
    Gat2Batch ga1{};
    {
        const int* o1[4] = {offs + b0, offs + b5, offs + b7, offs + b9};
        const float* i1[4] = {inv + b0, inv + b5, inv + b7, inv + b9};
        float* m1[4] = {L1m[0], L1m[2], L1m[4], L1m[6]};
        const int* o2[4] = {offs + b4, offs + b6, offs + b8, nullptr};
        const float* i2[4] = {inv + b4, inv + b6, inv + b8, nullptr};
        float* m2[4] = {L1m[1], L1m[3], L1m[5], nullptr};
        float* outs[4] = {x0l, x1l, x2l, x3l};
        int nsegs[4] = {n0, n1, n2, n3};
        int acc = 0;
        for (int i = 0; i < 4; i++) {
            ga1.t[i] = Gat2Task{o1[i], i1[i], (const float4*)m1[i],
                                o2[i], i2[i], (const float4*)m2[i],
                                outs[i], nsegs[i]};
            acc += (nsegs[i] * 8 + 255) / 256;
            ga1.blk_end[i] = acc;
        }
    }
    int ga1_blocks = ga1.blk_end[3];

    Gat2Batch ga2{};
    {
        const int* o1[4] = {offs + b0, offs + b1, offs + b2, offs + b3};
        const float* i1[4] = {inv + b0, inv + b1, inv + b2, inv + b3};
        float* m1[4] = {L2m[0], L2m[1], L2m[2], L2m[3]};
        const int* o2[4] = {nullptr, offs + b5, offs + b7, offs + b9};
        const float* i2[4] = {nullptr, inv + b5, inv + b7, inv + b9};
        float* m2[4] = {nullptr, L2m[5], L2m[7], L2m[9]};
        float* outs[4] = {out0, out1, out2, out3};
        int nsegs[4] = {n0, n1, n2, n3};
        int acc = 0;
        for (int i = 0; i < 4; i++) {
            ga2.t[i] = Gat2Task{o1[i], i1[i], (const float4*)m1[i],
                                o2[i], i2[i], (const float4*)m2[i],
                                outs[i], nsegs[i]};
            acc += (nsegs[i] * 8 + 255) / 256;
            ga2.blk_end[i] = acc;
        }
    }
    int ga2_blocks = ga2.blk_end[3];

    // ================= launch sequence =================
    int nb = (nscan + 1023) / 1024;
    cudaMemsetAsync(cnt, 0, (size_t)nscan * sizeof(int), 0);
    k_hist_batch<<<list_blocks, 256>>>(lb, cnt);
    k_scan1<<<nb, 256>>>(cnt, offs, bsum, nscan);
    k_scan2<<<1, 256>>>(bsum, nb);
    // Layer-1 GEMMs here (independent of CSR) so ncu's sample window hits it
    k_gemm_batch<<<gemm1_blocks, 256, GSMEM_BYTES>>>(gb1);
    k_scan3<<<(nscan + 255) / 256, 256>>>(offs, bsum, nscan);
    cudaMemcpyAsync(cur, offs, (size_t)nscan * sizeof(int),
                    cudaMemcpyDeviceToDevice, 0);
    k_scatter_batch<<<list_blocks, 256>>>(lb, cur, val);

    // Layer 1 edge phase
    k_segw_batch<<<sw1_blocks, 256>>>(sw1, val, w);
    k_gat2_batch<<<ga1_blocks, 256>>>(ga1, val, w);

    // Layer 2
    k_gemm_batch<<<gemm2_blocks, 256, GSMEM_BYTES>>>(gb2);
    k_segw_batch<<<sw2_blocks, 256>>>(sw2, val, w);
    k_gat2_batch<<<ga2_blocks, 256>>>(ga2, val, w);
}

// round 14
// speedup vs baseline: 1.1203x; 1.1203x over previous
#include <cuda_runtime.h>
#include <cuda_bf16.h>
#include <math.h>
#include <stdint.h>

#define SLOPE 0.2f

// ---------------- static scratch (no cudaMalloc allowed) ----------------
#define NMAX 200000
#define SEGMAX 1360000
#define EVMAX  5300000
#define MROWS  1360000            // total m rows across a batched gemm phase

__device__ __align__(16) float g_m[(size_t)MROWS * 64];     // per-gemm m regions
__device__ float g_d[(size_t)2 * MROWS + 16];               // per-gemm d1/d2 regions
__device__ __align__(16) float g_x0l[(size_t)100000 * 64];
__device__ __align__(16) float g_x1l[(size_t)200000 * 64];
__device__ __align__(16) float g_x2l[(size_t)150000 * 64];
__device__ __align__(16) float g_x3l[(size_t)50000 * 64];

__device__ int g_cnt[SEGMAX + 8];
__device__ int g_offs[SEGMAX + 8];
__device__ int g_cur[SEGMAX + 8];
__device__ int g_val[EVMAX];
__device__ float g_w[EVMAX];        // unnormalized exp weights (global CSR pos)
__device__ float g_inv[SEGMAX + 8]; // per-segment 1/sum (global segment index)
__device__ int g_bsum[4096];

// ---------------- batch descriptors (passed by value) ----------------
struct GemmTask { const float* x; const float* W; const float* a;
                  float* m; float* d1; float* d2; int n; };
struct GemmBatch { GemmTask t[10]; int blk_end[10]; };

struct SegwTask { const int* offs; const float* dS; const float* dO;
                  float* inv; int nseg; };
struct SegwBatch { SegwTask t[8]; int blk_end[8]; };

struct GatTask { const int* offs; const float* inv; const float4* m;
                 float* out; int nseg; int accum; };
struct GatBatch { GatTask t[8]; int blk_end[8]; };

struct ListBatch { const int* seg[10]; const int* oth[10];
                   int base[10]; int E[10]; int blk_end[10]; };

// ---------------- mma.sync bf16 GEMM (baseline PTX, works on sm_103) ------
// m = x @ W, split precision: x=xh+xl, W=Wh+Wl (bf16);
// D = xh@Wh + xh@Wl + xl@Wh in fp32.
// A fragments loaded DIRECTLY from global (no smem staging); only W^T hi/lo
// staged in static smem (~19KB). 3 CTAs/SM.
#define AST 72

__device__ __forceinline__ void mma16816(float* d, const uint32_t* a,
                                         uint32_t b0, uint32_t b1) {
    asm("mma.sync.aligned.m16n8k16.row.col.f32.bf16.bf16.f32 "
        "{%0,%1,%2,%3}, {%4,%5,%6,%7}, {%8,%9}, {%0,%1,%2,%3};"
        : "+f"(d[0]), "+f"(d[1]), "+f"(d[2]), "+f"(d[3])
        : "r"(a[0]), "r"(a[1]), "r"(a[2]), "r"(a[3]), "r"(b0), "r"(b1));
}

__device__ __forceinline__ uint32_t pack_hi(float2 f) {
    __nv_bfloat162 h = __halves2bfloat162(__float2bfloat16(f.x), __float2bfloat16(f.y));
    return *(uint32_t*)&h;
}
__device__ __forceinline__ uint32_t pack_lo(float2 f) {
    float rx = f.x - __bfloat162float(__float2bfloat16(f.x));
    float ry = f.y - __bfloat162float(__float2bfloat16(f.y));
    __nv_bfloat162 h = __halves2bfloat162(__float2bfloat16(rx), __float2bfloat16(ry));
    return *(uint32_t*)&h;
}

__global__ void __launch_bounds__(256, 3) k_gemm_batch(GemmBatch bat)
{
    __shared__ __nv_bfloat16 sBH[64 * AST];
    __shared__ __nv_bfloat16 sBL[64 * AST];
    __shared__ float as_[128];

    int id = 0;
    while ((int)blockIdx.x >= bat.blk_end[id]) id++;
    int bstart = id ? bat.blk_end[id - 1] : 0;
    const float* __restrict__ x = bat.t[id].x;
    const float* __restrict__ W = bat.t[id].W;
    float* __restrict__ m  = bat.t[id].m;
    float* __restrict__ d1 = bat.t[id].d1;
    float* __restrict__ d2 = bat.t[id].d2;
    int n = bat.t[id].n;

    int tid = threadIdx.x;
    int w = tid >> 5, lane = tid & 31;
    int g = lane >> 2, tig = lane & 3;
    int row0 = ((int)blockIdx.x - bstart) * 128;

    for (int i = tid; i < 4096; i += 256) {
        int k = i >> 6, c = i & 63;
        float v = W[i];
        __nv_bfloat16 h = __float2bfloat16(v);
        sBH[c * AST + k] = h;
        sBL[c * AST + k] = __float2bfloat16(v - __bfloat162float(h));
    }
    if (tid < 128) as_[tid] = bat.t[id].a[tid];

    int r0 = row0 + w * 16 + g;
    int r1 = r0 + 8;
    bool v0 = r0 < n, v1 = r1 < n;
    const float2 z2 = make_float2(0.f, 0.f);
    float2 raw[4][4];
#pragma unroll
    for (int ks = 0; ks < 4; ks++) {
        int c = ks * 16 + tig * 2;
        raw[ks][0] = v0 ? *(const float2*)&x[(size_t)r0 * 64 + c] : z2;
        raw[ks][1] = v1 ? *(const float2*)&x[(size_t)r1 * 64 + c] : z2;
        raw[ks][2] = v0 ? *(const float2*)&x[(size_t)r0 * 64 + c + 8] : z2;
        raw[ks][3] = v1 ? *(const float2*)&x[(size_t)r1 * 64 + c + 8] : z2;
    }
    __syncthreads();

    float D[8][4];
#pragma unroll
    for (int nt = 0; nt < 8; nt++)
#pragma unroll
        for (int j = 0; j < 4; j++) D[nt][j] = 0.f;

#pragma unroll
    for (int ks = 0; ks < 4; ks++) {
        uint32_t ah[4], al[4];
#pragma unroll
        for (int j = 0; j < 4; j++) {
            ah[j] = pack_hi(raw[ks][j]);
            al[j] = pack_lo(raw[ks][j]);
        }
#pragma unroll
        for (int nt = 0; nt < 8; nt++) {
            int bb = (nt * 8 + g) * AST + ks * 16 + tig * 2;
            uint32_t bh0 = *(uint32_t*)&sBH[bb];
            uint32_t bh1 = *(uint32_t*)&sBH[bb + 8];
            uint32_t bl0 = *(uint32_t*)&sBL[bb];
            uint32_t bl1 = *(uint32_t*)&sBL[bb + 8];
            mma16816(D[nt], ah, bh0, bh1);
            mma16816(D[nt], ah, bl0, bl1);
            mma16816(D[nt], al, bh0, bh1);
        }
    }

    float s1a = 0.f, s2a = 0.f, s1b = 0.f, s2b = 0.f;
#pragma unroll
    for (int nt = 0; nt < 8; nt++) {
        int c0 = nt * 8 + tig * 2;
        float2 a1p = *(float2*)&as_[c0];
        float2 a2p = *(float2*)&as_[64 + c0];
        s1a = fmaf(D[nt][0], a1p.x, fmaf(D[nt][1], a1p.y, s1a));
        s2a = fmaf(D[nt][0], a2p.x, fmaf(D[nt][1], a2p.y, s2a));
        s1b = fmaf(D[nt][2], a1p.x, fmaf(D[nt][3], a1p.y, s1b));
        s2b = fmaf(D[nt][2], a2p.x, fmaf(D[nt][3], a2p.y, s2b));
        if (v0)
            *(float2*)&m[(size_t)r0 * 64 + c0] = make_float2(D[nt][0], D[nt][1]);
        if (v1)
            *(float2*)&m[(size_t)r1 * 64 + c0] = make_float2(D[nt][2], D[nt][3]);
    }
#pragma unroll
    for (int off = 1; off < 4; off <<= 1) {
        s1a += __shfl_xor_sync(0xFFFFFFFFu, s1a, off);
        s2a += __shfl_xor_sync(0xFFFFFFFFu, s2a, off);
        s1b += __shfl_xor_sync(0xFFFFFFFFu, s1b, off);
        s2b += __shfl_xor_sync(0xFFFFFFFFu, s2b, off);
    }
    if (tig == 0) {
        if (v0) { d1[r0] = s1a; d2[r0] = s2a; }
        if (v1) { d1[r1] = s1b; d2[r1] = s2b; }
    }
}

// ---------------- CSR build (batched) ----------------
__global__ void k_hist_batch(ListBatch bat, int* __restrict__ cnt)
{
    int id = 0;
    while ((int)blockIdx.x >= bat.blk_end[id]) id++;
    int bstart = id ? bat.blk_end[id - 1] : 0;
    int e = ((int)blockIdx.x - bstart) * 256 + threadIdx.x;
    if (e >= bat.E[id]) return;
    atomicAdd(&cnt[bat.base[id] + bat.seg[id][e]], 1);
}

__global__ void k_scatter_batch(ListBatch bat, int* __restrict__ cur,
                                int* __restrict__ val)
{
    int id = 0;
    while ((int)blockIdx.x >= bat.blk_end[id]) id++;
    int bstart = id ? bat.blk_end[id - 1] : 0;
    int e = ((int)blockIdx.x - bstart) * 256 + threadIdx.x;
    if (e >= bat.E[id]) return;
    int pos = atomicAdd(&cur[bat.base[id] + bat.seg[id][e]], 1);
    val[pos] = bat.oth[id][e];
}

__global__ void k_scan1(const int* __restrict__ in, int* __restrict__ out,
                        int* __restrict__ bsum, int n)
{
    __shared__ int ts[256];
    int tid = threadIdx.x;
    int base = blockIdx.x * 1024 + tid * 4;
    int v[4]; int s = 0;
#pragma unroll
    for (int i = 0; i < 4; i++) {
        int idx = base + i;
        v[i] = (idx < n) ? in[idx] : 0;
        s += v[i];
    }
    ts[tid] = s; __syncthreads();
    for (int off = 1; off < 256; off <<= 1) {
        int t = (tid >= off) ? ts[tid - off] : 0;
        __syncthreads();
        ts[tid] += t;
        __syncthreads();
    }
    int excl = ts[tid] - s;
    if (tid == 255) bsum[blockIdx.x] = ts[255];
    int run = excl;
#pragma unroll
    for (int i = 0; i < 4; i++) {
        int idx = base + i;
        if (idx < n) out[idx] = run;
        run += v[i];
    }
}

__global__ void k_scan2(int* __restrict__ bsum, int nb)
{
    __shared__ int ts[256];
    __shared__ int carry;
    int tid = threadIdx.x;
    if (tid == 0) carry = 0;
    __syncthreads();
    for (int c0 = 0; c0 < nb; c0 += 256) {
        int i = c0 + tid;
        int v = (i < nb) ? bsum[i] : 0;
        ts[tid] = v; __syncthreads();
        for (int off = 1; off < 256; off <<= 1) {
            int t = (tid >= off) ? ts[tid - off] : 0;
            __syncthreads();
            ts[tid] += t;
            __syncthreads();
        }
        int excl = ts[tid] - v + carry;
        __syncthreads();
        if (i < nb) bsum[i] = excl;
        if (tid == 255) carry = excl + v;
        __syncthreads();
    }
}

// adds block sums AND initializes scatter cursors (replaces the D2D memcpy)
__global__ void k_scan3(int* __restrict__ out, int* __restrict__ cur,
                        const int* __restrict__ bsum, int n)
{
    int i = blockIdx.x * blockDim.x + threadIdx.x;
    if (i < n) {
        int v = out[i] + bsum[i >> 10];
        out[i] = v;
        cur[i] = v;
    }
}

// ---------------- per-segment softmax weights (batched) ----------------
__global__ void k_segw_batch(SegwBatch bat, const int* __restrict__ val,
                             float* __restrict__ w)
{
    int id = 0;
    while ((int)blockIdx.x >= bat.blk_end[id]) id++;
    int bstart = id ? bat.blk_end[id - 1] : 0;
    int s = ((int)blockIdx.x - bstart) * 256 + threadIdx.x;
    if (s >= bat.t[id].nseg) return;
    const int* offs = bat.t[id].offs;
    int p0 = offs[s], p1 = offs[s + 1];
    if (p0 == p1) return;
    float ds = bat.t[id].dS[s];
    const float* dO = bat.t[id].dO;
    float sum = 0.f;
    for (int p = p0; p < p1; p++) {
        int o = __ldg(&val[p]);
        float v = ds + __ldg(&dO[o]);
        v = (v > 0.f) ? v : SLOPE * v;
        float e = __expf(fminf(v, 80.f));
        w[p] = e;
        sum += e;
    }
    bat.t[id].inv[s] = 1.f / sum;
}

// ---------------- gather aggregation (batched) ----------------
// 8 lanes per segment, 32B per lane. accum=0: pure store covering every
// segment (zeros for empty); accum=1: RMW, empty segments skipped.
__global__ void k_gat_batch(GatBatch bat, const int* __restrict__ val,
                            const float* __restrict__ w)
{
    int id = 0;
    while ((int)blockIdx.x >= bat.blk_end[id]) id++;
    int bstart = id ? bat.blk_end[id - 1] : 0;
    int t = ((int)blockIdx.x - bstart) * 256 + threadIdx.x;
    int s = t >> 3;
    if (s >= bat.t[id].nseg) return;
    int g = t & 7;
    const int* offs = bat.t[id].offs;
    int p0 = offs[s], p1 = offs[s + 1];
    float4* dst = (float4*)&bat.t[id].out[(size_t)s * 64 + g * 8];
    int accum = bat.t[id].accum;

    if (p0 == p1) {
        if (!accum) {
            float4 z = make_float4(0.f, 0.f, 0.f, 0.f);
            dst[0] = z; dst[1] = z;
        }
        return;
    }

    const float4* m = bat.t[id].m;
    float4 A = make_float4(0.f, 0.f, 0.f, 0.f);
    float4 B = make_float4(0.f, 0.f, 0.f, 0.f);
    for (int p = p0; p < p1; p++) {
        float att = __ldg(&w[p]);
        int o = __ldg(&val[p]);
        float4 mv0 = __ldg(&m[o * 16 + g * 2]);
        float4 mv1 = __ldg(&m[o * 16 + g * 2 + 1]);
        A.x = fmaf(att, mv0.x, A.x); A.y = fmaf(att, mv0.y, A.y);
        A.z = fmaf(att, mv0.z, A.z); A.w = fmaf(att, mv0.w, A.w);
        B.x = fmaf(att, mv1.x, B.x); B.y = fmaf(att, mv1.y, B.y);
        B.z = fmaf(att, mv1.z, B.z); B.w = fmaf(att, mv1.w, B.w);
    }
    float iv = __ldg(&bat.t[id].inv[s]);
    A.x *= iv; A.y *= iv; A.z *= iv; A.w *= iv;
    B.x *= iv; B.y *= iv; B.z *= iv; B.w *= iv;

    if (accum) {
        float4 c0 = dst[0], c1 = dst[1];
        c0.x += A.x; c0.y += A.y; c0.z += A.z; c0.w += A.w;
        c1.x += B.x; c1.y += B.y; c1.z += B.z; c1.w += B.w;
        dst[0] = c0; dst[1] = c1;
    } else {
        dst[0] = A; dst[1] = B;
    }
}

extern "C" void kernel_launch(void* const* d_in, const int* in_sizes, int n_in,
                              void* d_out, int out_size)
{
    const float* x0   = (const float*)d_in[0];
    const float* x1   = (const float*)d_in[1];
    const float* x2   = (const float*)d_in[2];
    const float* x3   = (const float*)d_in[3];
    const float* hbsW = (const float*)d_in[4];
    const float* hbsA = (const float*)d_in[5];
    const float* hWs  = (const float*)d_in[6];
    const float* hWt  = (const float*)d_in[7];
    const float* hA   = (const float*)d_in[8];
    const int* a0r = (const int*)d_in[9];
    const int* a0c = (const int*)d_in[10];
    const int* a1r = (const int*)d_in[11];
    const int* a1c = (const int*)d_in[12];
    const int* a2r = (const int*)d_in[13];
    const int* a2c = (const int*)d_in[14];
    const int* c3r = (const int*)d_in[15];
    const int* c3c = (const int*)d_in[16];
    const int* i1r = (const int*)d_in[17];
    const int* i1c = (const int*)d_in[18];
    const int* i2r = (const int*)d_in[19];
    const int* i2c = (const int*)d_in[20];
    const int* i3r = (const int*)d_in[21];
    const int* i3c = (const int*)d_in[22];

    int n0 = in_sizes[0] / 64, n1 = in_sizes[1] / 64;
    int n2 = in_sizes[2] / 64, n3 = in_sizes[3] / 64;
    int Ea0 = in_sizes[9],  Ea1 = in_sizes[11], Ea2 = in_sizes[13];
    int Ec3 = in_sizes[15], Ei1 = in_sizes[17], Ei2 = in_sizes[19], Ei3 = in_sizes[21];

    float *mbuf, *dbuf, *x0l, *x1l, *x2l, *x3l, *w, *inv;
    int *cnt, *offs, *cur, *val, *bsum;
    cudaGetSymbolAddress((void**)&mbuf, g_m);
    cudaGetSymbolAddress((void**)&dbuf, g_d);
    cudaGetSymbolAddress((void**)&x0l, g_x0l);
    cudaGetSymbolAddress((void**)&x1l, g_x1l);
    cudaGetSymbolAddress((void**)&x2l, g_x2l);
    cudaGetSymbolAddress((void**)&x3l, g_x3l);
    cudaGetSymbolAddress((void**)&cnt,  g_cnt);
    cudaGetSymbolAddress((void**)&offs, g_offs);
    cudaGetSymbolAddress((void**)&cur,  g_cur);
    cudaGetSymbolAddress((void**)&val,  g_val);
    cudaGetSymbolAddress((void**)&w,    g_w);
    cudaGetSymbolAddress((void**)&inv,  g_inv);
    cudaGetSymbolAddress((void**)&bsum, g_bsum);

    float* out0 = (float*)d_out;
    float* out1 = out0 + (size_t)n0 * 64;
    float* out2 = out1 + (size_t)n1 * 64;
    float* out3 = out2 + (size_t)n2 * 64;

    // ------- CSR bases -------
    int b0 = 0;
    int b1 = b0 + n0;
    int b2 = b1 + n1;
    int b3 = b2 + n2;
    int b4 = b3 + n3;
    int b5 = b4 + n0;
    int b6 = b5 + n1;
    int b7 = b6 + n1;
    int b8 = b7 + n2;
    int b9 = b8 + n2;
    int segtot = b9 + n3;
    int nscan = segtot + 1;

    // ------- list batch (10 edge lists) -------
    ListBatch lb{};
    const int* segA[10] = {a0r, a1r, a2r, c3r, i1r, i1c, i2r, i2c, i3r, i3c};
    const int* othA[10] = {a0c, a1c, a2c, c3c, i1c, i1r, i2c, i2r, i3c, i3r};
    int baseA[10] = {b0, b1, b2, b3, b4, b5, b6, b7, b8, b9};
    int EA[10] = {Ea0, Ea1, Ea2, Ec3, Ei1, Ei1, Ei2, Ei2, Ei3, Ei3};
    {
        int acc = 0;
        for (int i = 0; i < 10; i++) {
            lb.seg[i] = segA[i]; lb.oth[i] = othA[i];
            lb.base[i] = baseA[i]; lb.E[i] = EA[i];
            acc += (EA[i] + 255) / 256;
            lb.blk_end[i] = acc;
        }
    }
    int list_blocks = lb.blk_end[9];

    // ------- GEMM batches -------
    const float* L1x[7] = {x0, x1, x0, x2, x1, x3, x2};
    const float* L1W[7] = {hbsW, hWs, hWt, hWs + 4096, hWt + 4096, hWs + 2 * 4096, hWt + 2 * 4096};
    const float* L1a[7] = {hbsA, hA, hA, hA + 128, hA + 128, hA + 2 * 128, hA + 2 * 128};
    int L1n[7] = {n0, n1, n0, n2, n1, n3, n2};
    GemmBatch gb1{};
    float* L1m[7]; float* L1d1[7]; float* L1d2[7];
    {
        size_t moff = 0; size_t doff = 0; int acc = 0;
        for (int i = 0; i < 7; i++) {
            L1m[i] = mbuf + moff * 64; moff += (size_t)L1n[i];
            L1d1[i] = dbuf + doff; L1d2[i] = dbuf + doff + L1n[i];
            doff += (size_t)2 * L1n[i];
            gb1.t[i] = GemmTask{L1x[i], L1W[i], L1a[i], L1m[i], L1d1[i], L1d2[i], L1n[i]};
            acc += (L1n[i] + 127) / 128;
            gb1.blk_end[i] = acc;
        }
        for (int i = 7; i < 10; i++) gb1.blk_end[i] = acc + 1 + i;
    }
    int gemm1_blocks = gb1.blk_end[6];

    const float* L2x[10] = {x0l, x1l, x2l, x3l, x1l, x0l, x2l, x1l, x3l, x2l};
    const float* L2W[10] = {hbsW + 4096, hbsW + 2 * 4096, hbsW + 3 * 4096, hbsW + 4 * 4096,
                            hWs + 3 * 4096, hWt + 3 * 4096, hWs + 4 * 4096, hWt + 4 * 4096,
                            hWs + 5 * 4096, hWt + 5 * 4096};
    const float* L2a[10] = {hbsA + 128, hbsA + 2 * 128, hbsA + 3 * 128, hbsA + 4 * 128,
                            hA + 3 * 128, hA + 3 * 128, hA + 4 * 128, hA + 4 * 128,
                            hA + 5 * 128, hA + 5 * 128};
    int L2n[10] = {n0, n1, n2, n3, n1, n0, n2, n1, n3, n2};
    GemmBatch gb2{};
    float* L2m[10]; float* L2d1[10]; float* L2d2[10];
    {
        size_t moff = 0; size_t doff = 0; int acc = 0;
        for (int i = 0; i < 10; i++) {
            L2m[i] = mbuf + moff * 64; moff += (size_t)L2n[i];
            L2d1[i] = dbuf + doff; L2d2[i] = dbuf + doff + L2n[i];
            doff += (size_t)2 * L2n[i];
            gb2.t[i] = GemmTask{L2x[i], L2W[i], L2a[i], L2m[i], L2d1[i], L2d2[i], L2n[i]};
            acc += (L2n[i] + 127) / 128;
            gb2.blk_end[i] = acc;
        }
    }
    int gemm2_blocks = gb2.blk_end[9];

    // ------- seg_w batches -------
    auto mk_segw = [&](SegwBatch& sb, int ntask,
                       const int* bases, const float** dS, const float** dO,
                       const int* nsegs) {
        int acc = 0;
        for (int i = 0; i < ntask; i++) {
            sb.t[i] = SegwTask{offs + bases[i], dS[i], dO[i], inv + bases[i], nsegs[i]};
            acc += (nsegs[i] + 255) / 256;
            sb.blk_end[i] = acc;
        }
        for (int i = ntask; i < 8; i++) sb.blk_end[i] = acc + 1 + i;
        return acc;
    };

    SegwBatch sw1{};
    {
        int bases[7]  = {b0, b4, b5, b6, b7, b8, b9};
        const float* dS[7] = {L1d1[0], L1d2[2], L1d2[1], L1d2[4], L1d2[3], L1d2[6], L1d2[5]};
        const float* dO[7] = {L1d2[0], L1d1[1], L1d1[2], L1d1[3], L1d1[4], L1d1[5], L1d1[6]};
        int nsegs[7] = {n0, n0, n1, n1, n2, n2, n3};
        mk_segw(sw1, 7, bases, dS, dO, nsegs);
    }
    int sw1_blocks = sw1.blk_end[6];

    SegwBatch sw2{};
    {
        int bases[7]  = {b0, b1, b2, b3, b5, b7, b9};
        const float* dS[7] = {L2d1[0], L2d1[1], L2d1[2], L2d1[3], L2d2[4], L2d2[6], L2d2[8]};
        const float* dO[7] = {L2d2[0], L2d2[1], L2d2[2], L2d2[3], L2d1[5], L2d1[7], L2d1[9]};
        int nsegs[7] = {n0, n1, n2, n3, n1, n2, n3};
        mk_segw(sw2, 7, bases, dS, dO, nsegs);
    }
    int sw2_blocks = sw2.blk_end[6];

    // ------- gat batches -------
    auto mk_gat = [&](GatBatch& gbat, int ntask, const int* bases,
                      float* const* ms, float* const* outs,
                      const int* nsegs, const int* accums) {
        int acc = 0;
        for (int i = 0; i < ntask; i++) {
            gbat.t[i] = GatTask{offs + bases[i], inv + bases[i],
                                (const float4*)ms[i], outs[i], nsegs[i], accums[i]};
            acc += (nsegs[i] * 8 + 255) / 256;
            gbat.blk_end[i] = acc;
        }
        for (int i = ntask; i < 8; i++) gbat.blk_end[i] = acc + 1 + i;
        return acc;
    };

    GatBatch gw1{};
    {
        int bases[4] = {b0, b5, b7, b9};
        float* ms[4] = {L1m[0], L1m[2], L1m[4], L1m[6]};
        float* outs[4] = {x0l, x1l, x2l, x3l};
        int nsegs[4] = {n0, n1, n2, n3};
        int accums[4] = {0, 0, 0, 0};
        mk_gat(gw1, 4, bases, ms, outs, nsegs, accums);
    }
    int gw1_blocks = gw1.blk_end[3];

    GatBatch gw2{};
    {
        int bases[3] = {b4, b6, b8};
        float* ms[3] = {L1m[1], L1m[3], L1m[5]};
        float* outs[3] = {x0l, x1l, x2l};
        int nsegs[3] = {n0, n1, n2};
        int accums[3] = {1, 1, 1};
        mk_gat(gw2, 3, bases, ms, outs, nsegs, accums);
    }
    int gw2_blocks = gw2.blk_end[2];

    GatBatch gw3{};
    {
        int bases[4] = {b0, b1, b2, b3};
        float* ms[4] = {L2m[0], L2m[1], L2m[2], L2m[3]};
        float* outs[4] = {out0, out1, out2, out3};
        int nsegs[4] = {n0, n1, n2, n3};
        int accums[4] = {0, 0, 0, 0};
        mk_gat(gw3, 4, bases, ms, outs, nsegs, accums);
    }
    int gw3_blocks = gw3.blk_end[3];

    GatBatch gw4{};
    {
        int bases[3] = {b5, b7, b9};
        float* ms[3] = {L2m[5], L2m[7], L2m[9]};
        float* outs[3] = {out1, out2, out3};
        int nsegs[3] = {n1, n2, n3};
        int accums[3] = {1, 1, 1};
        mk_gat(gw4, 3, bases, ms, outs, nsegs, accums);
    }
    int gw4_blocks = gw4.blk_end[2];

    // ================= launch sequence =================
    int nb = (nscan + 1023) / 1024;
    cudaMemsetAsync(cnt, 0, (size_t)nscan * sizeof(int), 0);
    k_hist_batch<<<list_blocks, 256>>>(lb, cnt);
    k_scan1<<<nb, 256>>>(cnt, offs, bsum, nscan);
    k_scan2<<<1, 256>>>(bsum, nb);
    // Layer-1 GEMMs here (independent of CSR) so ncu's sample window hits it
    k_gemm_batch<<<gemm1_blocks, 256>>>(gb1);
    k_scan3<<<(nscan + 255) / 256, 256>>>(offs, cur, bsum, nscan);
    k_scatter_batch<<<list_blocks, 256>>>(lb, cur, val);

    // Layer 1 edge phase
    k_segw_batch<<<sw1_blocks, 256>>>(sw1, val, w);
    k_gat_batch<<<gw1_blocks, 256>>>(gw1, val, w);
    k_gat_batch<<<gw2_blocks, 256>>>(gw2, val, w);

    // Layer 2
    k_gemm_batch<<<gemm2_blocks, 256>>>(gb2);
    k_segw_batch<<<sw2_blocks, 256>>>(sw2, val, w);
    k_gat_batch<<<gw3_blocks, 256>>>(gw3, val, w);
    k_gat_batch<<<gw4_blocks, 256>>>(gw4, val, w);
}

// round 15
// speedup vs baseline: 1.1237x; 1.0031x over previous
#include <cuda_runtime.h>
#include <cuda_bf16.h>
#include <math.h>
#include <stdint.h>

#define SLOPE 0.2f

// ---------------- static scratch (no cudaMalloc allowed) ----------------
#define NMAX 200000
#define SEGMAX 1360000
#define EVMAX  5300000
#define MROWS  1360000            // total m rows across a batched gemm phase

__device__ __align__(16) float g_m[(size_t)MROWS * 64];     // per-gemm m regions
__device__ float g_d[(size_t)2 * MROWS + 16];               // per-gemm d1/d2 regions
__device__ __align__(16) float g_x0l[(size_t)100000 * 64];
__device__ __align__(16) float g_x1l[(size_t)200000 * 64];
__device__ __align__(16) float g_x2l[(size_t)150000 * 64];
__device__ __align__(16) float g_x3l[(size_t)50000 * 64];

__device__ int g_cnt[SEGMAX + 8];
__device__ int g_offs[SEGMAX + 8];
__device__ int g_cur[SEGMAX + 8];
__device__ int g_val[EVMAX];
__device__ float g_w[EVMAX];        // unnormalized exp weights (global CSR pos)
__device__ float g_inv[SEGMAX + 8]; // per-segment 1/sum (global segment index)
__device__ int g_bsum[4096];

// ---------------- batch descriptors (passed by value) ----------------
struct GemmTask { const float* x; const float* W; const float* a;
                  float* m; float* d1; float* d2; int n; };
struct GemmBatch { GemmTask t[10]; int blk_end[10]; };

struct SegwTask { const int* offs; const float* dS; const float* dO;
                  float* inv; int nseg; };
struct SegwBatch { SegwTask t[8]; int blk_end[8]; };

struct GatTask { const int* offs; const float* inv; const float4* m;
                 float* out; int nseg; int accum; };
struct GatBatch { GatTask t[8]; int blk_end[8]; };

struct ListBatch { const int* seg[10]; const int* oth[10];
                   int base[10]; int E[10]; int blk_end[10]; };

// ---------------- mma.sync bf16 GEMM (baseline PTX, works on sm_103) ------
// m = x @ W, split precision: x=xh+xl, W=Wh+Wl (bf16);
// D = xh@Wh + xh@Wl + xl@Wh in fp32.
// A fragments loaded DIRECTLY from global (no smem staging); only W^T hi/lo
// staged in static smem (~19KB). 3 CTAs/SM.
#define AST 72

__device__ __forceinline__ void mma16816(float* d, const uint32_t* a,
                                         uint32_t b0, uint32_t b1) {
    asm("mma.sync.aligned.m16n8k16.row.col.f32.bf16.bf16.f32 "
        "{%0,%1,%2,%3}, {%4,%5,%6,%7}, {%8,%9}, {%0,%1,%2,%3};"
        : "+f"(d[0]), "+f"(d[1]), "+f"(d[2]), "+f"(d[3])
        : "r"(a[0]), "r"(a[1]), "r"(a[2]), "r"(a[3]), "r"(b0), "r"(b1));
}

__device__ __forceinline__ uint32_t pack_hi(float2 f) {
    __nv_bfloat162 h = __halves2bfloat162(__float2bfloat16(f.x), __float2bfloat16(f.y));
    return *(uint32_t*)&h;
}
__device__ __forceinline__ uint32_t pack_lo(float2 f) {
    float rx = f.x - __bfloat162float(__float2bfloat16(f.x));
    float ry = f.y - __bfloat162float(__float2bfloat16(f.y));
    __nv_bfloat162 h = __halves2bfloat162(__float2bfloat16(rx), __float2bfloat16(ry));
    return *(uint32_t*)&h;
}

__global__ void __launch_bounds__(256, 3) k_gemm_batch(GemmBatch bat)
{
    __shared__ __nv_bfloat16 sBH[64 * AST];
    __shared__ __nv_bfloat16 sBL[64 * AST];
    __shared__ float as_[128];

    int id = 0;
    while ((int)blockIdx.x >= bat.blk_end[id]) id++;
    int bstart = id ? bat.blk_end[id - 1] : 0;
    const float* __restrict__ x = bat.t[id].x;
    const float* __restrict__ W = bat.t[id].W;
    float* __restrict__ m  = bat.t[id].m;
    float* __restrict__ d1 = bat.t[id].d1;
    float* __restrict__ d2 = bat.t[id].d2;
    int n = bat.t[id].n;

    int tid = threadIdx.x;
    int w = tid >> 5, lane = tid & 31;
    int g = lane >> 2, tig = lane & 3;
    int row0 = ((int)blockIdx.x - bstart) * 128;

    for (int i = tid; i < 4096; i += 256) {
        int k = i >> 6, c = i & 63;
        float v = W[i];
        __nv_bfloat16 h = __float2bfloat16(v);
        sBH[c * AST + k] = h;
        sBL[c * AST + k] = __float2bfloat16(v - __bfloat162float(h));
    }
    if (tid < 128) as_[tid] = bat.t[id].a[tid];

    int r0 = row0 + w * 16 + g;
    int r1 = r0 + 8;
    bool v0 = r0 < n, v1 = r1 < n;
    const float2 z2 = make_float2(0.f, 0.f);
    float2 raw[4][4];
#pragma unroll
    for (int ks = 0; ks < 4; ks++) {
        int c = ks * 16 + tig * 2;
        raw[ks][0] = v0 ? *(const float2*)&x[(size_t)r0 * 64 + c] : z2;
        raw[ks][1] = v1 ? *(const float2*)&x[(size_t)r1 * 64 + c] : z2;
        raw[ks][2] = v0 ? *(const float2*)&x[(size_t)r0 * 64 + c + 8] : z2;
        raw[ks][3] = v1 ? *(const float2*)&x[(size_t)r1 * 64 + c + 8] : z2;
    }
    __syncthreads();

    float D[8][4];
#pragma unroll
    for (int nt = 0; nt < 8; nt++)
#pragma unroll
        for (int j = 0; j < 4; j++) D[nt][j] = 0.f;

#pragma unroll
    for (int ks = 0; ks < 4; ks++) {
        uint32_t ah[4], al[4];
#pragma unroll
        for (int j = 0; j < 4; j++) {
            ah[j] = pack_hi(raw[ks][j]);
            al[j] = pack_lo(raw[ks][j]);
        }
#pragma unroll
        for (int nt = 0; nt < 8; nt++) {
            int bb = (nt * 8 + g) * AST + ks * 16 + tig * 2;
            uint32_t bh0 = *(uint32_t*)&sBH[bb];
            uint32_t bh1 = *(uint32_t*)&sBH[bb + 8];
            uint32_t bl0 = *(uint32_t*)&sBL[bb];
            uint32_t bl1 = *(uint32_t*)&sBL[bb + 8];
            mma16816(D[nt], ah, bh0, bh1);
            mma16816(D[nt], ah, bl0, bl1);
            mma16816(D[nt], al, bh0, bh1);
        }
    }

    float s1a = 0.f, s2a = 0.f, s1b = 0.f, s2b = 0.f;
#pragma unroll
    for (int nt = 0; nt < 8; nt++) {
        int c0 = nt * 8 + tig * 2;
        float2 a1p = *(float2*)&as_[c0];
        float2 a2p = *(float2*)&as_[64 + c0];
        s1a = fmaf(D[nt][0], a1p.x, fmaf(D[nt][1], a1p.y, s1a));
        s2a = fmaf(D[nt][0], a2p.x, fmaf(D[nt][1], a2p.y, s2a));
        s1b = fmaf(D[nt][2], a1p.x, fmaf(D[nt][3], a1p.y, s1b));
        s2b = fmaf(D[nt][2], a2p.x, fmaf(D[nt][3], a2p.y, s2b));
        if (v0)
            *(float2*)&m[(size_t)r0 * 64 + c0] = make_float2(D[nt][0], D[nt][1]);
        if (v1)
            *(float2*)&m[(size_t)r1 * 64 + c0] = make_float2(D[nt][2], D[nt][3]);
    }
#pragma unroll
    for (int off = 1; off < 4; off <<= 1) {
        s1a += __shfl_xor_sync(0xFFFFFFFFu, s1a, off);
        s2a += __shfl_xor_sync(0xFFFFFFFFu, s2a, off);
        s1b += __shfl_xor_sync(0xFFFFFFFFu, s1b, off);
        s2b += __shfl_xor_sync(0xFFFFFFFFu, s2b, off);
    }
    if (tig == 0) {
        if (v0) { d1[r0] = s1a; d2[r0] = s2a; }
        if (v1) { d1[r1] = s1b; d2[r1] = s2b; }
    }
}

// ---------------- CSR build (batched) ----------------
__global__ void k_hist_batch(ListBatch bat, int* __restrict__ cnt)
{
    int id = 0;
    while ((int)blockIdx.x >= bat.blk_end[id]) id++;
    int bstart = id ? bat.blk_end[id - 1] : 0;
    int e = ((int)blockIdx.x - bstart) * 256 + threadIdx.x;
    if (e >= bat.E[id]) return;
    atomicAdd(&cnt[bat.base[id] + bat.seg[id][e]], 1);
}

__global__ void k_scatter_batch(ListBatch bat, int* __restrict__ cur,
                                int* __restrict__ val)
{
    int id = 0;
    while ((int)blockIdx.x >= bat.blk_end[id]) id++;
    int bstart = id ? bat.blk_end[id - 1] : 0;
    int e = ((int)blockIdx.x - bstart) * 256 + threadIdx.x;
    if (e >= bat.E[id]) return;
    int pos = atomicAdd(&cur[bat.base[id] + bat.seg[id][e]], 1);
    val[pos] = bat.oth[id][e];
}

__global__ void k_scan1(const int* __restrict__ in, int* __restrict__ out,
                        int* __restrict__ bsum, int n)
{
    __shared__ int ts[256];
    int tid = threadIdx.x;
    int base = blockIdx.x * 1024 + tid * 4;
    int v[4]; int s = 0;
#pragma unroll
    for (int i = 0; i < 4; i++) {
        int idx = base + i;
        v[i] = (idx < n) ? in[idx] : 0;
        s += v[i];
    }
    ts[tid] = s; __syncthreads();
    for (int off = 1; off < 256; off <<= 1) {
        int t = (tid >= off) ? ts[tid - off] : 0;
        __syncthreads();
        ts[tid] += t;
        __syncthreads();
    }
    int excl = ts[tid] - s;
    if (tid == 255) bsum[blockIdx.x] = ts[255];
    int run = excl;
#pragma unroll
    for (int i = 0; i < 4; i++) {
        int idx = base + i;
        if (idx < n) out[idx] = run;
        run += v[i];
    }
}

__global__ void k_scan2(int* __restrict__ bsum, int nb)
{
    __shared__ int ts[256];
    __shared__ int carry;
    int tid = threadIdx.x;
    if (tid == 0) carry = 0;
    __syncthreads();
    for (int c0 = 0; c0 < nb; c0 += 256) {
        int i = c0 + tid;
        int v = (i < nb) ? bsum[i] : 0;
        ts[tid] = v; __syncthreads();
        for (int off = 1; off < 256; off <<= 1) {
            int t = (tid >= off) ? ts[tid - off] : 0;
            __syncthreads();
            ts[tid] += t;
            __syncthreads();
        }
        int excl = ts[tid] - v + carry;
        __syncthreads();
        if (i < nb) bsum[i] = excl;
        if (tid == 255) carry = excl + v;
        __syncthreads();
    }
}

// adds block sums AND initializes scatter cursors (replaces the D2D memcpy)
__global__ void k_scan3(int* __restrict__ out, int* __restrict__ cur,
                        const int* __restrict__ bsum, int n)
{
    int i = blockIdx.x * blockDim.x + threadIdx.x;
    if (i < n) {
        int v = out[i] + bsum[i >> 10];
        out[i] = v;
        cur[i] = v;
    }
}

// ---------------- per-segment softmax weights (batched) ----------------
__global__ void k_segw_batch(SegwBatch bat, const int* __restrict__ val,
                             float* __restrict__ w)
{
    int id = 0;
    while ((int)blockIdx.x >= bat.blk_end[id]) id++;
    int bstart = id ? bat.blk_end[id - 1] : 0;
    int s = ((int)blockIdx.x - bstart) * 256 + threadIdx.x;
    if (s >= bat.t[id].nseg) return;
    const int* offs = bat.t[id].offs;
    int p0 = offs[s], p1 = offs[s + 1];
    if (p0 == p1) return;
    float ds = bat.t[id].dS[s];
    const float* dO = bat.t[id].dO;
    float sum = 0.f;
    for (int p = p0; p < p1; p++) {
        int o = __ldg(&val[p]);
        float v = ds + __ldg(&dO[o]);
        v = (v > 0.f) ? v : SLOPE * v;
        float e = __expf(fminf(v, 80.f));
        w[p] = e;
        sum += e;
    }
    bat.t[id].inv[s] = 1.f / sum;
}

// ---------------- gather aggregation (batched) ----------------
// 8 lanes per segment, 32B per lane. accum=0: pure store covering every
// segment (zeros for empty); accum=1: RMW, empty segments skipped.
__global__ void k_gat_batch(GatBatch bat, const int* __restrict__ val,
                            const float* __restrict__ w)
{
    int id = 0;
    while ((int)blockIdx.x >= bat.blk_end[id]) id++;
    int bstart = id ? bat.blk_end[id - 1] : 0;
    int t = ((int)blockIdx.x - bstart) * 256 + threadIdx.x;
    int s = t >> 3;
    if (s >= bat.t[id].nseg) return;
    int g = t & 7;
    const int* offs = bat.t[id].offs;
    int p0 = offs[s], p1 = offs[s + 1];
    float4* dst = (float4*)&bat.t[id].out[(size_t)s * 64 + g * 8];
    int accum = bat.t[id].accum;

    if (p0 == p1) {
        if (!accum) {
            float4 z = make_float4(0.f, 0.f, 0.f, 0.f);
            dst[0] = z; dst[1] = z;
        }
        return;
    }

    const float4* m = bat.t[id].m;
    float4 A = make_float4(0.f, 0.f, 0.f, 0.f);
    float4 B = make_float4(0.f, 0.f, 0.f, 0.f);
    for (int p = p0; p < p1; p++) {
        float att = __ldg(&w[p]);
        int o = __ldg(&val[p]);
        float4 mv0 = __ldg(&m[o * 16 + g * 2]);
        float4 mv1 = __ldg(&m[o * 16 + g * 2 + 1]);
        A.x = fmaf(att, mv0.x, A.x); A.y = fmaf(att, mv0.y, A.y);
        A.z = fmaf(att, mv0.z, A.z); A.w = fmaf(att, mv0.w, A.w);
        B.x = fmaf(att, mv1.x, B.x); B.y = fmaf(att, mv1.y, B.y);
        B.z = fmaf(att, mv1.z, B.z); B.w = fmaf(att, mv1.w, B.w);
    }
    float iv = __ldg(&bat.t[id].inv[s]);
    A.x *= iv; A.y *= iv; A.z *= iv; A.w *= iv;
    B.x *= iv; B.y *= iv; B.z *= iv; B.w *= iv;

    if (accum) {
        float4 c0 = dst[0], c1 = dst[1];
        c0.x += A.x; c0.y += A.y; c0.z += A.z; c0.w += A.w;
        c1.x += B.x; c1.y += B.y; c1.z += B.z; c1.w += B.w;
        dst[0] = c0; dst[1] = c1;
    } else {
        dst[0] = A; dst[1] = B;
    }
}

extern "C" void kernel_launch(void* const* d_in, const int* in_sizes, int n_in,
                              void* d_out, int out_size)
{
    // lazily-created side stream + events for fork/join inside graph capture
    static cudaStream_t s_build = nullptr;
    static cudaEvent_t ev_fork = nullptr, ev_join = nullptr;
    if (!s_build) {
        cudaStreamCreateWithFlags(&s_build, cudaStreamNonBlocking);
        cudaEventCreateWithFlags(&ev_fork, cudaEventDisableTiming);
        cudaEventCreateWithFlags(&ev_join, cudaEventDisableTiming);
    }

    const float* x0   = (const float*)d_in[0];
    const float* x1   = (const float*)d_in[1];
    const float* x2   = (const float*)d_in[2];
    const float* x3   = (const float*)d_in[3];
    const float* hbsW = (const float*)d_in[4];
    const float* hbsA = (const float*)d_in[5];
    const float* hWs  = (const float*)d_in[6];
    const float* hWt  = (const float*)d_in[7];
    const float* hA   = (const float*)d_in[8];
    const int* a0r = (const int*)d_in[9];
    const int* a0c = (const int*)d_in[10];
    const int* a1r = (const int*)d_in[11];
    const int* a1c = (const int*)d_in[12];
    const int* a2r = (const int*)d_in[13];
    const int* a2c = (const int*)d_in[14];
    const int* c3r = (const int*)d_in[15];
    const int* c3c = (const int*)d_in[16];
    const int* i1r = (const int*)d_in[17];
    const int* i1c = (const int*)d_in[18];
    const int* i2r = (const int*)d_in[19];
    const int* i2c = (const int*)d_in[20];
    const int* i3r = (const int*)d_in[21];
    const int* i3c = (const int*)d_in[22];

    int n0 = in_sizes[0] / 64, n1 = in_sizes[1] / 64;
    int n2 = in_sizes[2] / 64, n3 = in_sizes[3] / 64;
    int Ea0 = in_sizes[9],  Ea1 = in_sizes[11], Ea2 = in_sizes[13];
    int Ec3 = in_sizes[15], Ei1 = in_sizes[17], Ei2 = in_sizes[19], Ei3 = in_sizes[21];

    float *mbuf, *dbuf, *x0l, *x1l, *x2l, *x3l, *w, *inv;
    int *cnt, *offs, *cur, *val, *bsum;
    cudaGetSymbolAddress((void**)&mbuf, g_m);
    cudaGetSymbolAddress((void**)&dbuf, g_d);
    cudaGetSymbolAddress((void**)&x0l, g_x0l);
    cudaGetSymbolAddress((void**)&x1l, g_x1l);
    cudaGetSymbolAddress((void**)&x2l, g_x2l);
    cudaGetSymbolAddress((void**)&x3l, g_x3l);
    cudaGetSymbolAddress((void**)&cnt,  g_cnt);
    cudaGetSymbolAddress((void**)&offs, g_offs);
    cudaGetSymbolAddress((void**)&cur,  g_cur);
    cudaGetSymbolAddress((void**)&val,  g_val);
    cudaGetSymbolAddress((void**)&w,    g_w);
    cudaGetSymbolAddress((void**)&inv,  g_inv);
    cudaGetSymbolAddress((void**)&bsum, g_bsum);

    float* out0 = (float*)d_out;
    float* out1 = out0 + (size_t)n0 * 64;
    float* out2 = out1 + (size_t)n1 * 64;
    float* out3 = out2 + (size_t)n2 * 64;

    // ------- CSR bases -------
    int b0 = 0;
    int b1 = b0 + n0;
    int b2 = b1 + n1;
    int b3 = b2 + n2;
    int b4 = b3 + n3;
    int b5 = b4 + n0;
    int b6 = b5 + n1;
    int b7 = b6 + n1;
    int b8 = b7 + n2;
    int b9 = b8 + n2;
    int segtot = b9 + n3;
    int nscan = segtot + 1;

    // ------- list batch (10 edge lists) -------
    ListBatch lb{};
    const int* segA[10] = {a0r, a1r, a2r, c3r, i1r, i1c, i2r, i2c, i3r, i3c};
    const int* othA[10] = {a0c, a1c, a2c, c3c, i1c, i1r, i2c, i2r, i3c, i3r};
    int baseA[10] = {b0, b1, b2, b3, b4, b5, b6, b7, b8, b9};
    int EA[10] = {Ea0, Ea1, Ea2, Ec3, Ei1, Ei1, Ei2, Ei2, Ei3, Ei3};
    {
        int acc = 0;
        for (int i = 0; i < 10; i++) {
            lb.seg[i] = segA[i]; lb.oth[i] = othA[i];
            lb.base[i] = baseA[i]; lb.E[i] = EA[i];
            acc += (EA[i] + 255) / 256;
            lb.blk_end[i] = acc;
        }
    }
    int list_blocks = lb.blk_end[9];

    // ------- GEMM batches -------
    const float* L1x[7] = {x0, x1, x0, x2, x1, x3, x2};
    const float* L1W[7] = {hbsW, hWs, hWt, hWs + 4096, hWt + 4096, hWs + 2 * 4096, hWt + 2 * 4096};
    const float* L1a[7] = {hbsA, hA, hA, hA + 128, hA + 128, hA + 2 * 128, hA + 2 * 128};
    int L1n[7] = {n0, n1, n0, n2, n1, n3, n2};
    GemmBatch gb1{};
    float* L1m[7]; float* L1d1[7]; float* L1d2[7];
    {
        size_t moff = 0; size_t doff = 0; int acc = 0;
        for (int i = 0; i < 7; i++) {
            L1m[i] = mbuf + moff * 64; moff += (size_t)L1n[i];
            L1d1[i] = dbuf + doff; L1d2[i] = dbuf + doff + L1n[i];
            doff += (size_t)2 * L1n[i];
            gb1.t[i] = GemmTask{L1x[i], L1W[i], L1a[i], L1m[i], L1d1[i], L1d2[i], L1n[i]};
            acc += (L1n[i] + 127) / 128;
            gb1.blk_end[i] = acc;
        }
        for (int i = 7; i < 10; i++) gb1.blk_end[i] = acc + 1 + i;
    }
    int gemm1_blocks = gb1.blk_end[6];

    const float* L2x[10] = {x0l, x1l, x2l, x3l, x1l, x0l, x2l, x1l, x3l, x2l};
    const float* L2W[10] = {hbsW + 4096, hbsW + 2 * 4096, hbsW + 3 * 4096, hbsW + 4 * 4096,
                            hWs + 3 * 4096, hWt + 3 * 4096, hWs + 4 * 4096, hWt + 4 * 4096,
                            hWs + 5 * 4096, hWt + 5 * 4096};
    const float* L2a[10] = {hbsA + 128, hbsA + 2 * 128, hbsA + 3 * 128, hbsA + 4 * 128,
                            hA + 3 * 128, hA + 3 * 128, hA + 4 * 128, hA + 4 * 128,
                            hA + 5 * 128, hA + 5 * 128};
    int L2n[10] = {n0, n1, n2, n3, n1, n0, n2, n1, n3, n2};
    GemmBatch gb2{};
    float* L2m[10]; float* L2d1[10]; float* L2d2[10];
    {
        size_t moff = 0; size_t doff = 0; int acc = 0;
        for (int i = 0; i < 10; i++) {
            L2m[i] = mbuf + moff * 64; moff += (size_t)L2n[i];
            L2d1[i] = dbuf + doff; L2d2[i] = dbuf + doff + L2n[i];
            doff += (size_t)2 * L2n[i];
            gb2.t[i] = GemmTask{L2x[i], L2W[i], L2a[i], L2m[i], L2d1[i], L2d2[i], L2n[i]};
            acc += (L2n[i] + 127) / 128;
            gb2.blk_end[i] = acc;
        }
    }
    int gemm2_blocks = gb2.blk_end[9];

    // ------- seg_w batches -------
    auto mk_segw = [&](SegwBatch& sb, int ntask,
                       const int* bases, const float** dS, const float** dO,
                       const int* nsegs) {
        int acc = 0;
        for (int i = 0; i < ntask; i++) {
            sb.t[i] = SegwTask{offs + bases[i], dS[i], dO[i], inv + bases[i], nsegs[i]};
            acc += (nsegs[i] + 255) / 256;
            sb.blk_end[i] = acc;
        }
        for (int i = ntask; i < 8; i++) sb.blk_end[i] = acc + 1 + i;
        return acc;
    };

    SegwBatch sw1{};
    {
        int bases[7]  = {b0, b4, b5, b6, b7, b8, b9};
        const float* dS[7] = {L1d1[0], L1d2[2], L1d2[1], L1d2[4], L1d2[3], L1d2[6], L1d2[5]};
        const float* dO[7] = {L1d2[0], L1d1[1], L1d1[2], L1d1[3], L1d1[4], L1d1[5], L1d1[6]};
        int nsegs[7] = {n0, n0, n1, n1, n2, n2, n3};
        mk_segw(sw1, 7, bases, dS, dO, nsegs);
    }
    int sw1_blocks = sw1.blk_end[6];

    SegwBatch sw2{};
    {
        int bases[7]  = {b0, b1, b2, b3, b5, b7, b9};
        const float* dS[7] = {L2d1[0], L2d1[1], L2d1[2], L2d1[3], L2d2[4], L2d2[6], L2d2[8]};
        const float* dO[7] = {L2d2[0], L2d2[1], L2d2[2], L2d2[3], L2d1[5], L2d1[7], L2d1[9]};
        int nsegs[7] = {n0, n1, n2, n3, n1, n2, n3};
        mk_segw(sw2, 7, bases, dS, dO, nsegs);
    }
    int sw2_blocks = sw2.blk_end[6];

    // ------- gat batches -------
    auto mk_gat = [&](GatBatch& gbat, int ntask, const int* bases,
                      float* const* ms, float* const* outs,
                      const int* nsegs, const int* accums) {
        int acc = 0;
        for (int i = 0; i < ntask; i++) {
            gbat.t[i] = GatTask{offs + bases[i], inv + bases[i],
                                (const float4*)ms[i], outs[i], nsegs[i], accums[i]};
            acc += (nsegs[i] * 8 + 255) / 256;
            gbat.blk_end[i] = acc;
        }
        for (int i = ntask; i < 8; i++) gbat.blk_end[i] = acc + 1 + i;
        return acc;
    };

    GatBatch gw1{};
    {
        int bases[4] = {b0, b5, b7, b9};
        float* ms[4] = {L1m[0], L1m[2], L1m[4], L1m[6]};
        float* outs[4] = {x0l, x1l, x2l, x3l};
        int nsegs[4] = {n0, n1, n2, n3};
        int accums[4] = {0, 0, 0, 0};
        mk_gat(gw1, 4, bases, ms, outs, nsegs, accums);
    }
    int gw1_blocks = gw1.blk_end[3];

    GatBatch gw2{};
    {
        int bases[3] = {b4, b6, b8};
        float* ms[3] = {L1m[1], L1m[3], L1m[5]};
        float* outs[3] = {x0l, x1l, x2l};
        int nsegs[3] = {n0, n1, n2};
        int accums[3] = {1, 1, 1};
        mk_gat(gw2, 3, bases, ms, outs, nsegs, accums);
    }
    int gw2_blocks = gw2.blk_end[2];

    GatBatch gw3{};
    {
        int bases[4] = {b0, b1, b2, b3};
        float* ms[4] = {L2m[0], L2m[1], L2m[2], L2m[3]};
        float* outs[4] = {out0, out1, out2, out3};
        int nsegs[4] = {n0, n1, n2, n3};
        int accums[4] = {0, 0, 0, 0};
        mk_gat(gw3, 4, bases, ms, outs, nsegs, accums);
    }
    int gw3_blocks = gw3.blk_end[3];

    GatBatch gw4{};
    {
        int bases[3] = {b5, b7, b9};
        float* ms[3] = {L2m[5], L2m[7], L2m[9]};
        float* outs[3] = {out1, out2, out3};
        int nsegs[3] = {n1, n2, n3};
        int accums[3] = {1, 1, 1};
        mk_gat(gw4, 3, bases, ms, outs, nsegs, accums);
    }
    int gw4_blocks = gw4.blk_end[2];

    // ================= launch sequence =================
    int nb = (nscan + 1023) / 1024;

    // fork: CSR build runs on s_build, concurrent with the layer-1 GEMM batch
    cudaEventRecord(ev_fork, 0);
    cudaStreamWaitEvent(s_build, ev_fork, 0);
    cudaMemsetAsync(cnt, 0, (size_t)nscan * sizeof(int), s_build);
    k_hist_batch<<<list_blocks, 256, 0, s_build>>>(lb, cnt);
    k_scan1<<<nb, 256, 0, s_build>>>(cnt, offs, bsum, nscan);
    k_scan2<<<1, 256, 0, s_build>>>(bsum, nb);
    k_scan3<<<(nscan + 255) / 256, 256, 0, s_build>>>(offs, cur, bsum, nscan);
    k_scatter_batch<<<list_blocks, 256, 0, s_build>>>(lb, cur, val);
    cudaEventRecord(ev_join, s_build);

    // main stream: layer-1 GEMMs (independent of CSR build)
    k_gemm_batch<<<gemm1_blocks, 256>>>(gb1);

    // join: edge phase needs both GEMM outputs and the CSR
    cudaStreamWaitEvent(0, ev_join, 0);

    // Layer 1 edge phase
    k_segw_batch<<<sw1_blocks, 256>>>(sw1, val, w);
    k_gat_batch<<<gw1_blocks, 256>>>(gw1, val, w);
    k_gat_batch<<<gw2_blocks, 256>>>(gw2, val, w);

    // Layer 2
    k_gemm_batch<<<gemm2_blocks, 256>>>(gb2);
    k_segw_batch<<<sw2_blocks, 256>>>(sw2, val, w);
    k_gat_batch<<<gw3_blocks, 256>>>(gw3, val, w);
    k_gat_batch<<<gw4_blocks, 256>>>(gw4, val, w);
}

// round 17
// speedup vs baseline: 1.1731x; 1.0439x over previous
#include <cuda_runtime.h>
#include <cuda_bf16.h>
#include <math.h>
#include <stdint.h>

#define SLOPE 0.2f

// ---------------- static scratch (no cudaMalloc allowed) ----------------
#define NMAX 200000
#define SEGMAX 1360000
#define EVMAX  5300000
#define MROWS  1360000

__device__ __align__(16) float g_m[(size_t)MROWS * 64];
__device__ float g_d[(size_t)2 * MROWS + 16];
__device__ __align__(16) float g_x0l[(size_t)100000 * 64];
__device__ __align__(16) float g_x1l[(size_t)200000 * 64];
__device__ __align__(16) float g_x2l[(size_t)150000 * 64];
__device__ __align__(16) float g_x3l[(size_t)50000 * 64];

__device__ int g_cnt[SEGMAX + 8];
__device__ int g_offs[SEGMAX + 8];
__device__ int g_cur[SEGMAX + 8];
__device__ int g_val[EVMAX];
__device__ float g_w[EVMAX];
__device__ float g_inv[SEGMAX + 8];
__device__ int g_bsum[4096];
__device__ float g_wa[3 * 64];        // W@a2 vectors for the 3 matvec tasks

// ---------------- batch descriptors (passed by value) ----------------
struct GemmTask { const float* x; const float* W; const float* a;
                  float* m; float* d1; float* d2; int n; };
struct GemmBatch { GemmTask t[10]; int blk_end[10]; };

struct SegwTask { const int* offs; const float* dS; const float* dO;
                  float* inv; int nseg; };
struct SegwBatch { SegwTask t[8]; int blk_end[8]; };

struct GatTask { const int* offs; const float* inv; const float4* m;
                 float* out; int nseg; int accum; };
struct GatBatch { GatTask t[8]; int blk_end[8]; };

struct ListBatch { const int* seg[10]; const int* oth[10];
                   int base[10]; int E[10]; int blk_end[10]; };

struct WvTask { const float* W; const float* a2; float* wa; };
struct WvBatch { WvTask t[3]; };

struct DotvTask { const float* x; const float* wa; float* out; int n; };
struct DotvBatch { DotvTask t[3]; int blk_end[3]; };

// ---------------- mma.sync bf16 GEMM (baseline PTX, works on sm_103) ------
#define AST 72

__device__ __forceinline__ void mma16816(float* d, const uint32_t* a,
                                         uint32_t b0, uint32_t b1) {
    asm("mma.sync.aligned.m16n8k16.row.col.f32.bf16.bf16.f32 "
        "{%0,%1,%2,%3}, {%4,%5,%6,%7}, {%8,%9}, {%0,%1,%2,%3};"
        : "+f"(d[0]), "+f"(d[1]), "+f"(d[2]), "+f"(d[3])
        : "r"(a[0]), "r"(a[1]), "r"(a[2]), "r"(a[3]), "r"(b0), "r"(b1));
}

__device__ __forceinline__ uint32_t pack_hi(float2 f) {
    __nv_bfloat162 h = __halves2bfloat162(__float2bfloat16(f.x), __float2bfloat16(f.y));
    return *(uint32_t*)&h;
}
__device__ __forceinline__ uint32_t pack_lo(float2 f) {
    float rx = f.x - __bfloat162float(__float2bfloat16(f.x));
    float ry = f.y - __bfloat162float(__float2bfloat16(f.y));
    __nv_bfloat162 h = __halves2bfloat162(__float2bfloat16(rx), __float2bfloat16(ry));
    return *(uint32_t*)&h;
}

__global__ void __launch_bounds__(256, 3) k_gemm_batch(GemmBatch bat)
{
    __shared__ __nv_bfloat16 sBH[64 * AST];
    __shared__ __nv_bfloat16 sBL[64 * AST];
    __shared__ float as_[128];

    int id = 0;
    while ((int)blockIdx.x >= bat.blk_end[id]) id++;
    int bstart = id ? bat.blk_end[id - 1] : 0;
    const float* __restrict__ x = bat.t[id].x;
    const float* __restrict__ W = bat.t[id].W;
    float* __restrict__ m  = bat.t[id].m;
    float* __restrict__ d1 = bat.t[id].d1;
    float* __restrict__ d2 = bat.t[id].d2;
    int n = bat.t[id].n;

    int tid = threadIdx.x;
    int w = tid >> 5, lane = tid & 31;
    int g = lane >> 2, tig = lane & 3;
    int row0 = ((int)blockIdx.x - bstart) * 128;

    for (int i = tid; i < 4096; i += 256) {
        int k = i >> 6, c = i & 63;
        float v = W[i];
        __nv_bfloat16 h = __float2bfloat16(v);
        sBH[c * AST + k] = h;
        sBL[c * AST + k] = __float2bfloat16(v - __bfloat162float(h));
    }
    if (tid < 128) as_[tid] = bat.t[id].a[tid];

    int r0 = row0 + w * 16 + g;
    int r1 = r0 + 8;
    bool v0 = r0 < n, v1 = r1 < n;
    const float2 z2 = make_float2(0.f, 0.f);
    float2 raw[4][4];
#pragma unroll
    for (int ks = 0; ks < 4; ks++) {
        int c = ks * 16 + tig * 2;
        raw[ks][0] = v0 ? *(const float2*)&x[(size_t)r0 * 64 + c] : z2;
        raw[ks][1] = v1 ? *(const float2*)&x[(size_t)r1 * 64 + c] : z2;
        raw[ks][2] = v0 ? *(const float2*)&x[(size_t)r0 * 64 + c + 8] : z2;
        raw[ks][3] = v1 ? *(const float2*)&x[(size_t)r1 * 64 + c + 8] : z2;
    }
    __syncthreads();

    float D[8][4];
#pragma unroll
    for (int nt = 0; nt < 8; nt++)
#pragma unroll
        for (int j = 0; j < 4; j++) D[nt][j] = 0.f;

#pragma unroll
    for (int ks = 0; ks < 4; ks++) {
        uint32_t ah[4], al[4];
#pragma unroll
        for (int j = 0; j < 4; j++) {
            ah[j] = pack_hi(raw[ks][j]);
            al[j] = pack_lo(raw[ks][j]);
        }
#pragma unroll
        for (int nt = 0; nt < 8; nt++) {
            int bb = (nt * 8 + g) * AST + ks * 16 + tig * 2;
            uint32_t bh0 = *(uint32_t*)&sBH[bb];
            uint32_t bh1 = *(uint32_t*)&sBH[bb + 8];
            uint32_t bl0 = *(uint32_t*)&sBL[bb];
            uint32_t bl1 = *(uint32_t*)&sBL[bb + 8];
            mma16816(D[nt], ah, bh0, bh1);
            mma16816(D[nt], ah, bl0, bl1);
            mma16816(D[nt], al, bh0, bh1);
        }
    }

    float s1a = 0.f, s2a = 0.f, s1b = 0.f, s2b = 0.f;
#pragma unroll
    for (int nt = 0; nt < 8; nt++) {
        int c0 = nt * 8 + tig * 2;
        float2 a1p = *(float2*)&as_[c0];
        float2 a2p = *(float2*)&as_[64 + c0];
        s1a = fmaf(D[nt][0], a1p.x, fmaf(D[nt][1], a1p.y, s1a));
        s2a = fmaf(D[nt][0], a2p.x, fmaf(D[nt][1], a2p.y, s2a));
        s1b = fmaf(D[nt][2], a1p.x, fmaf(D[nt][3], a1p.y, s1b));
        s2b = fmaf(D[nt][2], a2p.x, fmaf(D[nt][3], a2p.y, s2b));
        if (v0)
            *(float2*)&m[(size_t)r0 * 64 + c0] = make_float2(D[nt][0], D[nt][1]);
        if (v1)
            *(float2*)&m[(size_t)r1 * 64 + c0] = make_float2(D[nt][2], D[nt][3]);
    }
#pragma unroll
    for (int off = 1; off < 4; off <<= 1) {
        s1a += __shfl_xor_sync(0xFFFFFFFFu, s1a, off);
        s2a += __shfl_xor_sync(0xFFFFFFFFu, s2a, off);
        s1b += __shfl_xor_sync(0xFFFFFFFFu, s1b, off);
        s2b += __shfl_xor_sync(0xFFFFFFFFu, s2b, off);
    }
    if (tig == 0) {
        if (v0) { d1[r0] = s1a; d2[r0] = s2a; }
        if (v1) { d1[r1] = s1b; d2[r1] = s2b; }
    }
}

// ---------------- matvec replacement for m-unused GEMMs ----------------
// wa = W @ a2  (3 tasks, 64 outputs each)
__global__ void k_wv(WvBatch bat)
{
    int id = blockIdx.x;            // 0..2
    int k = threadIdx.x;            // 0..63
    const float* W = bat.t[id].W;
    const float* a2 = bat.t[id].a2;
    float s = 0.f;
    for (int c = 0; c < 64; c++) s = fmaf(__ldg(&W[k * 64 + c]), __ldg(&a2[c]), s);
    bat.t[id].wa[k] = s;
}

// out[row] = x[row] . wa   (fp32; replaces full GEMM whose m was unused)
__global__ void k_dotv_batch(DotvBatch bat)
{
    __shared__ float was[64];
    int id = 0;
    while ((int)blockIdx.x >= bat.blk_end[id]) id++;
    int bstart = id ? bat.blk_end[id - 1] : 0;
    if (threadIdx.x < 64) was[threadIdx.x] = bat.t[id].wa[threadIdx.x];
    __syncthreads();
    int row = ((int)blockIdx.x - bstart) * 256 + threadIdx.x;
    if (row >= bat.t[id].n) return;
    const float* xr = bat.t[id].x + (size_t)row * 64;
    float s = 0.f;
#pragma unroll
    for (int j = 0; j < 16; j++) {
        float4 v = __ldg((const float4*)(xr + j * 4));
        s = fmaf(v.x, was[j * 4], s);
        s = fmaf(v.y, was[j * 4 + 1], s);
        s = fmaf(v.z, was[j * 4 + 2], s);
        s = fmaf(v.w, was[j * 4 + 3], s);
    }
    bat.t[id].out[row] = s;
}

// ---------------- CSR build (batched) ----------------
__global__ void k_hist_batch(ListBatch bat, int* __restrict__ cnt)
{
    int id = 0;
    while ((int)blockIdx.x >= bat.blk_end[id]) id++;
    int bstart = id ? bat.blk_end[id - 1] : 0;
    int e = ((int)blockIdx.x - bstart) * 256 + threadIdx.x;
    if (e >= bat.E[id]) return;
    atomicAdd(&cnt[bat.base[id] + bat.seg[id][e]], 1);
}

__global__ void k_scatter_batch(ListBatch bat, int* __restrict__ cur,
                                int* __restrict__ val)
{
    int id = 0;
    while ((int)blockIdx.x >= bat.blk_end[id]) id++;
    int bstart = id ? bat.blk_end[id - 1] : 0;
    int e = ((int)blockIdx.x - bstart) * 256 + threadIdx.x;
    if (e >= bat.E[id]) return;
    int pos = atomicAdd(&cur[bat.base[id] + bat.seg[id][e]], 1);
    val[pos] = bat.oth[id][e];
}

__global__ void k_scan1(const int* __restrict__ in, int* __restrict__ out,
                        int* __restrict__ bsum, int n)
{
    __shared__ int ts[256];
    int tid = threadIdx.x;
    int base = blockIdx.x * 1024 + tid * 4;
    int v[4]; int s = 0;
#pragma unroll
    for (int i = 0; i < 4; i++) {
        int idx = base + i;
        v[i] = (idx < n) ? in[idx] : 0;
        s += v[i];
    }
    ts[tid] = s; __syncthreads();
    for (int off = 1; off < 256; off <<= 1) {
        int t = (tid >= off) ? ts[tid - off] : 0;
        __syncthreads();
        ts[tid] += t;
        __syncthreads();
    }
    int excl = ts[tid] - s;
    if (tid == 255) bsum[blockIdx.x] = ts[255];
    int run = excl;
#pragma unroll
    for (int i = 0; i < 4; i++) {
        int idx = base + i;
        if (idx < n) out[idx] = run;
        run += v[i];
    }
}

__global__ void k_scan2(int* __restrict__ bsum, int nb)
{
    __shared__ int ts[256];
    __shared__ int carry;
    int tid = threadIdx.x;
    if (tid == 0) carry = 0;
    __syncthreads();
    for (int c0 = 0; c0 < nb; c0 += 256) {
        int i = c0 + tid;
        int v = (i < nb) ? bsum[i] : 0;
        ts[tid] = v; __syncthreads();
        for (int off = 1; off < 256; off <<= 1) {
            int t = (tid >= off) ? ts[tid - off] : 0;
            __syncthreads();
            ts[tid] += t;
            __syncthreads();
        }
        int excl = ts[tid] - v + carry;
        __syncthreads();
        if (i < nb) bsum[i] = excl;
        if (tid == 255) carry = excl + v;
        __syncthreads();
    }
}

__global__ void k_scan3(int* __restrict__ out, int* __restrict__ cur,
                        const int* __restrict__ bsum, int n)
{
    int i = blockIdx.x * blockDim.x + threadIdx.x;
    if (i < n) {
        int v = out[i] + bsum[i >> 10];
        out[i] = v;
        cur[i] = v;
    }
}

// ---------------- per-segment softmax weights (batched) ----------------
__global__ void k_segw_batch(SegwBatch bat, const int* __restrict__ val,
                             float* __restrict__ w)
{
    int id = 0;
    while ((int)blockIdx.x >= bat.blk_end[id]) id++;
    int bstart = id ? bat.blk_end[id - 1] : 0;
    int s = ((int)blockIdx.x - bstart) * 256 + threadIdx.x;
    if (s >= bat.t[id].nseg) return;
    const int* offs = bat.t[id].offs;
    int p0 = offs[s], p1 = offs[s + 1];
    if (p0 == p1) return;
    float ds = bat.t[id].dS[s];
    const float* dO = bat.t[id].dO;
    float sum = 0.f;
    for (int p = p0; p < p1; p++) {
        int o = __ldg(&val[p]);
        float v = ds + __ldg(&dO[o]);
        v = (v > 0.f) ? v : SLOPE * v;
        float e = __expf(fminf(v, 80.f));
        w[p] = e;
        sum += e;
    }
    bat.t[id].inv[s] = 1.f / sum;
}

// ---------------- gather aggregation (batched) ----------------
__global__ void k_gat_batch(GatBatch bat, const int* __restrict__ val,
                            const float* __restrict__ w)
{
    int id = 0;
    while ((int)blockIdx.x >= bat.blk_end[id]) id++;
    int bstart = id ? bat.blk_end[id - 1] : 0;
    int t = ((int)blockIdx.x - bstart) * 256 + threadIdx.x;
    int s = t >> 3;
    if (s >= bat.t[id].nseg) return;
    int g = t & 7;
    const int* offs = bat.t[id].offs;
    int p0 = offs[s], p1 = offs[s + 1];
    float4* dst = (float4*)&bat.t[id].out[(size_t)s * 64 + g * 8];
    int accum = bat.t[id].accum;

    if (p0 == p1) {
        if (!accum) {
            float4 z = make_float4(0.f, 0.f, 0.f, 0.f);
            dst[0] = z; dst[1] = z;
        }
        return;
    }

    const float4* m = bat.t[id].m;
    float4 A = make_float4(0.f, 0.f, 0.f, 0.f);
    float4 B = make_float4(0.f, 0.f, 0.f, 0.f);
    for (int p = p0; p < p1; p++) {
        float att = __ldg(&w[p]);
        int o = __ldg(&val[p]);
        float4 mv0 = __ldg(&m[o * 16 + g * 2]);
        float4 mv1 = __ldg(&m[o * 16 + g * 2 + 1]);
        A.x = fmaf(att, mv0.x, A.x); A.y = fmaf(att, mv0.y, A.y);
        A.z = fmaf(att, mv0.z, A.z); A.w = fmaf(att, mv0.w, A.w);
        B.x = fmaf(att, mv1.x, B.x); B.y = fmaf(att, mv1.y, B.y);
        B.z = fmaf(att, mv1.z, B.z); B.w = fmaf(att, mv1.w, B.w);
    }
    float iv = __ldg(&bat.t[id].inv[s]);
    A.x *= iv; A.y *= iv; A.z *= iv; A.w *= iv;
    B.x *= iv; B.y *= iv; B.z *= iv; B.w *= iv;

    if (accum) {
        float4 c0 = dst[0], c1 = dst[1];
        c0.x += A.x; c0.y += A.y; c0.z += A.z; c0.w += A.w;
        c1.x += B.x; c1.y += B.y; c1.z += B.z; c1.w += B.w;
        dst[0] = c0; dst[1] = c1;
    } else {
        dst[0] = A; dst[1] = B;
    }
}

extern "C" void kernel_launch(void* const* d_in, const int* in_sizes, int n_in,
                              void* d_out, int out_size)
{
    static cudaStream_t s_build = nullptr;
    static cudaEvent_t ev_fork = nullptr, ev_join = nullptr;
    static cudaEvent_t ev_fork2 = nullptr, ev_join2 = nullptr;
    if (!s_build) {
        cudaStreamCreateWithFlags(&s_build, cudaStreamNonBlocking);
        cudaEventCreateWithFlags(&ev_fork, cudaEventDisableTiming);
        cudaEventCreateWithFlags(&ev_join, cudaEventDisableTiming);
        cudaEventCreateWithFlags(&ev_fork2, cudaEventDisableTiming);
        cudaEventCreateWithFlags(&ev_join2, cudaEventDisableTiming);
    }

    const float* x0   = (const float*)d_in[0];
    const float* x1   = (const float*)d_in[1];
    const float* x2   = (const float*)d_in[2];
    const float* x3   = (const float*)d_in[3];
    const float* hbsW = (const float*)d_in[4];
    const float* hbsA = (const float*)d_in[5];
    const float* hWs  = (const float*)d_in[6];
    const float* hWt  = (const float*)d_in[7];
    const float* hA   = (const float*)d_in[8];
    const int* a0r = (const int*)d_in[9];
    const int* a0c = (const int*)d_in[10];
    const int* a1r = (const int*)d_in[11];
    const int* a1c = (const int*)d_in[12];
    const int* a2r = (const int*)d_in[13];
    const int* a2c = (const int*)d_in[14];
    const int* c3r = (const int*)d_in[15];
    const int* c3c = (const int*)d_in[16];
    const int* i1r = (const int*)d_in[17];
    const int* i1c = (const int*)d_in[18];
    const int* i2r = (const int*)d_in[19];
    const int* i2c = (const int*)d_in[20];
    const int* i3r = (const int*)d_in[21];
    const int* i3c = (const int*)d_in[22];

    int n0 = in_sizes[0] / 64, n1 = in_sizes[1] / 64;
    int n2 = in_sizes[2] / 64, n3 = in_sizes[3] / 64;
    int Ea0 = in_sizes[9],  Ea1 = in_sizes[11], Ea2 = in_sizes[13];
    int Ec3 = in_sizes[15], Ei1 = in_sizes[17], Ei2 = in_sizes[19], Ei3 = in_sizes[21];

    float *mbuf, *dbuf, *x0l, *x1l, *x2l, *x3l, *w, *inv, *wa;
    int *cnt, *offs, *cur, *val, *bsum;
    cudaGetSymbolAddress((void**)&mbuf, g_m);
    cudaGetSymbolAddress((void**)&dbuf, g_d);
    cudaGetSymbolAddress((void**)&x0l, g_x0l);
    cudaGetSymbolAddress((void**)&x1l, g_x1l);
    cudaGetSymbolAddress((void**)&x2l, g_x2l);
    cudaGetSymbolAddress((void**)&x3l, g_x3l);
    cudaGetSymbolAddress((void**)&cnt,  g_cnt);
    cudaGetSymbolAddress((void**)&offs, g_offs);
    cudaGetSymbolAddress((void**)&cur,  g_cur);
    cudaGetSymbolAddress((void**)&val,  g_val);
    cudaGetSymbolAddress((void**)&w,    g_w);
    cudaGetSymbolAddress((void**)&inv,  g_inv);
    cudaGetSymbolAddress((void**)&bsum, g_bsum);
    cudaGetSymbolAddress((void**)&wa,   g_wa);

    float* out0 = (float*)d_out;
    float* out1 = out0 + (size_t)n0 * 64;
    float* out2 = out1 + (size_t)n1 * 64;
    float* out3 = out2 + (size_t)n2 * 64;

    // ------- CSR bases -------
    int b0 = 0;
    int b1 = b0 + n0;
    int b2 = b1 + n1;
    int b3 = b2 + n2;
    int b4 = b3 + n3;
    int b5 = b4 + n0;
    int b6 = b5 + n1;
    int b7 = b6 + n1;
    int b8 = b7 + n2;
    int b9 = b8 + n2;
    int segtot = b9 + n3;
    int nscan = segtot + 1;

    // ------- list batch (10 edge lists) -------
    ListBatch lb{};
    const int* segA[10] = {a0r, a1r, a2r, c3r, i1r, i1c, i2r, i2c, i3r, i3c};
    const int* othA[10] = {a0c, a1c, a2c, c3c, i1c, i1r, i2c, i2r, i3c, i3r};
    int baseA[10] = {b0, b1, b2, b3, b4, b5, b6, b7, b8, b9};
    int EA[10] = {Ea0, Ea1, Ea2, Ec3, Ei1, Ei1, Ei2, Ei2, Ei3, Ei3};
    {
        int acc = 0;
        for (int i = 0; i < 10; i++) {
            lb.seg[i] = segA[i]; lb.oth[i] = othA[i];
            lb.base[i] = baseA[i]; lb.E[i] = EA[i];
            acc += (EA[i] + 255) / 256;
            lb.blk_end[i] = acc;
        }
    }
    int list_blocks = lb.blk_end[9];

    // ------- Layer-1 GEMM batch (7 tasks, unchanged) -------
    const float* L1x[7] = {x0, x1, x0, x2, x1, x3, x2};
    const float* L1W[7] = {hbsW, hWs, hWt, hWs + 4096, hWt + 4096, hWs + 2 * 4096, hWt + 2 * 4096};
    const float* L1a[7] = {hbsA, hA, hA, hA + 128, hA + 128, hA + 2 * 128, hA + 2 * 128};
    int L1n[7] = {n0, n1, n0, n2, n1, n3, n2};
    GemmBatch gb1{};
    float* L1m[7]; float* L1d1[7]; float* L1d2[7];
    {
        size_t moff = 0; size_t doff = 0; int acc = 0;
        for (int i = 0; i < 7; i++) {
            L1m[i] = mbuf + moff * 64; moff += (size_t)L1n[i];
            L1d1[i] = dbuf + doff; L1d2[i] = dbuf + doff + L1n[i];
            doff += (size_t)2 * L1n[i];
            gb1.t[i] = GemmTask{L1x[i], L1W[i], L1a[i], L1m[i], L1d1[i], L1d2[i], L1n[i]};
            acc += (L1n[i] + 127) / 128;
            gb1.blk_end[i] = acc;
        }
        for (int i = 7; i < 10; i++) gb1.blk_end[i] = acc + 1 + i;
    }
    int gemm1_blocks = gb1.blk_end[6];

    // ------- Layer-2 GEMM batch: 7 tasks (the 3 m-unused GEMMs replaced
    //         by matvec). Tasks: y00,y11,y22,y33 + tm sides of y01,y12,y23.
    const float* L2x[7] = {x0l, x1l, x2l, x3l, x0l, x1l, x2l};
    const float* L2W[7] = {hbsW + 4096, hbsW + 2 * 4096, hbsW + 3 * 4096, hbsW + 4 * 4096,
                           hWt + 3 * 4096, hWt + 4 * 4096, hWt + 5 * 4096};
    const float* L2a[7] = {hbsA + 128, hbsA + 2 * 128, hbsA + 3 * 128, hbsA + 4 * 128,
                           hA + 3 * 128, hA + 4 * 128, hA + 5 * 128};
    int L2n[7] = {n0, n1, n2, n3, n0, n1, n2};
    GemmBatch gb2{};
    float* L2m[7]; float* L2d1[7]; float* L2d2[7];
    size_t l2_doff_end = 0;
    {
        size_t moff = 0; size_t doff = 0; int acc = 0;
        for (int i = 0; i < 7; i++) {
            L2m[i] = mbuf + moff * 64; moff += (size_t)L2n[i];
            L2d1[i] = dbuf + doff; L2d2[i] = dbuf + doff + L2n[i];
            doff += (size_t)2 * L2n[i];
            gb2.t[i] = GemmTask{L2x[i], L2W[i], L2a[i], L2m[i], L2d1[i], L2d2[i], L2n[i]};
            acc += (L2n[i] + 127) / 128;
            gb2.blk_end[i] = acc;
        }
        for (int i = 7; i < 10; i++) gb2.blk_end[i] = acc + 1 + i;
        l2_doff_end = doff;
    }
    int gemm2_blocks = gb2.blk_end[6];

    // ------- matvec tasks: dS for y01/y12/y23 = x @ (Ws @ a2) -------
    WvBatch wv{};
    wv.t[0] = WvTask{hWs + 3 * 4096, hA + 3 * 128 + 64, wa + 0 * 64};
    wv.t[1] = WvTask{hWs + 4 * 4096, hA + 4 * 128 + 64, wa + 1 * 64};
    wv.t[2] = WvTask{hWs + 5 * 4096, hA + 5 * 128 + 64, wa + 2 * 64};

    float* dv0 = dbuf + l2_doff_end;
    float* dv1 = dv0 + n1;
    float* dv2 = dv1 + n2;
    DotvBatch dvb{};
    {
        const float* xs[3] = {x1l, x2l, x3l};
        float* outs[3] = {dv0, dv1, dv2};
        int ns[3] = {n1, n2, n3};
        int acc = 0;
        for (int i = 0; i < 3; i++) {
            dvb.t[i] = DotvTask{xs[i], wa + i * 64, outs[i], ns[i]};
            acc += (ns[i] + 255) / 256;
            dvb.blk_end[i] = acc;
        }
    }
    int dotv_blocks = dvb.blk_end[2];

    // ------- seg_w batches -------
    auto mk_segw = [&](SegwBatch& sb, int ntask,
                       const int* bases, const float** dS, const float** dO,
                       const int* nsegs) {
        int acc = 0;
        for (int i = 0; i < ntask; i++) {
            sb.t[i] = SegwTask{offs + bases[i], dS[i], dO[i], inv + bases[i], nsegs[i]};
            acc += (nsegs[i] + 255) / 256;
            sb.blk_end[i] = acc;
        }
        for (int i = ntask; i < 8; i++) sb.blk_end[i] = acc + 1 + i;
        return acc;
    };

    SegwBatch sw1{};
    {
        int bases[7]  = {b0, b4, b5, b6, b7, b8, b9};
        const float* dS[7] = {L1d1[0], L1d2[2], L1d2[1], L1d2[4], L1d2[3], L1d2[6], L1d2[5]};
        const float* dO[7] = {L1d2[0], L1d1[1], L1d1[2], L1d1[3], L1d1[4], L1d1[5], L1d1[6]};
        int nsegs[7] = {n0, n0, n1, n1, n2, n2, n3};
        mk_segw(sw1, 7, bases, dS, dO, nsegs);
    }
    int sw1_blocks = sw1.blk_end[6];

    // L2 segw: y00(b0), y11(b1), y22(b2), y33(b3) from gemm tasks 0-3;
    // y01(b5): dS=dv0 (x1l side), dO=L2d1[4] (x0l@hWt3 @ a1);
    // y12(b7): dS=dv1, dO=L2d1[5]; y23(b9): dS=dv2, dO=L2d1[6].
    SegwBatch sw2{};
    {
        int bases[7]  = {b0, b1, b2, b3, b5, b7, b9};
        const float* dS[7] = {L2d1[0], L2d1[1], L2d1[2], L2d1[3], dv0, dv1, dv2};
        const float* dO[7] = {L2d2[0], L2d2[1], L2d2[2], L2d2[3], L2d1[4], L2d1[5], L2d1[6]};
        int nsegs[7] = {n0, n1, n2, n3, n1, n2, n3};
        mk_segw(sw2, 7, bases, dS, dO, nsegs);
    }
    int sw2_blocks = sw2.blk_end[6];

    // ------- gat batches -------
    auto mk_gat = [&](GatBatch& gbat, int ntask, const int* bases,
                      float* const* ms, float* const* outs,
                      const int* nsegs, const int* accums) {
        int acc = 0;
        for (int i = 0; i < ntask; i++) {
            gbat.t[i] = GatTask{offs + bases[i], inv + bases[i],
                                (const float4*)ms[i], outs[i], nsegs[i], accums[i]};
            acc += (nsegs[i] * 8 + 255) / 256;
            gbat.blk_end[i] = acc;
        }
        for (int i = ntask; i < 8; i++) gbat.blk_end[i] = acc + 1 + i;
        return acc;
    };

    GatBatch gw1{};
    {
        int bases[4] = {b0, b5, b7, b9};
        float* ms[4] = {L1m[0], L1m[2], L1m[4], L1m[6]};
        float* outs[4] = {x0l, x1l, x2l, x3l};
        int nsegs[4] = {n0, n1, n2, n3};
        int accums[4] = {0, 0, 0, 0};
        mk_gat(gw1, 4, bases, ms, outs, nsegs, accums);
    }
    int gw1_blocks = gw1.blk_end[3];

    GatBatch gw2{};
    {
        int bases[3] = {b4, b6, b8};
        float* ms[3] = {L1m[1], L1m[3], L1m[5]};
        float* outs[3] = {x0l, x1l, x2l};
        int nsegs[3] = {n0, n1, n2};
        int accums[3] = {1, 1, 1};
        mk_gat(gw2, 3, bases, ms, outs, nsegs, accums);
    }
    int gw2_blocks = gw2.blk_end[2];

    GatBatch gw3{};
    {
        int bases[4] = {b0, b1, b2, b3};
        float* ms[4] = {L2m[0], L2m[1], L2m[2], L2m[3]};
        float* outs[4] = {out0, out1, out2, out3};
        int nsegs[4] = {n0, n1, n2, n3};
        int accums[4] = {0, 0, 0, 0};
        mk_gat(gw3, 4, bases, ms, outs, nsegs, accums);
    }
    int gw3_blocks = gw3.blk_end[3];

    // y01 gathers m of task4 (x0l@hWt3), y12 task5, y23 task6
    GatBatch gw4{};
    {
        int bases[3] = {b5, b7, b9};
        float* ms[3] = {L2m[4], L2m[5], L2m[6]};
        float* outs[3] = {out1, out2, out3};
        int nsegs[3] = {n1, n2, n3};
        int accums[3] = {1, 1, 1};
        mk_gat(gw4, 3, bases, ms, outs, nsegs, accums);
    }
    int gw4_blocks = gw4.blk_end[2];

    // ================= launch sequence =================
    int nb = (nscan + 1023) / 1024;

    // fork 1: CSR build concurrent with layer-1 GEMMs
    cudaEventRecord(ev_fork, 0);
    cudaStreamWaitEvent(s_build, ev_fork, 0);
    cudaMemsetAsync(cnt, 0, (size_t)nscan * sizeof(int), s_build);
    k_hist_batch<<<list_blocks, 256, 0, s_build>>>(lb, cnt);
    k_scan1<<<nb, 256, 0, s_build>>>(cnt, offs, bsum, nscan);
    k_scan2<<<1, 256, 0, s_build>>>(bsum, nb);
    k_scan3<<<(nscan + 255) / 256, 256, 0, s_build>>>(offs, cur, bsum, nscan);
    k_scatter_batch<<<list_blocks, 256, 0, s_build>>>(lb, cur, val);
    cudaEventRecord(ev_join, s_build);

    k_gemm_batch<<<gemm1_blocks, 256>>>(gb1);
    cudaStreamWaitEvent(0, ev_join, 0);

    // Layer 1 edge phase
    k_segw_batch<<<sw1_blocks, 256>>>(sw1, val, w);
    k_gat_batch<<<gw1_blocks, 256>>>(gw1, val, w);
    k_gat_batch<<<gw2_blocks, 256>>>(gw2, val, w);

    // fork 2: matvec path concurrent with layer-2 GEMMs
    cudaEventRecord(ev_fork2, 0);
    cudaStreamWaitEvent(s_build, ev_fork2, 0);
    k_wv<<<3, 64, 0, s_build>>>(wv);
    k_dotv_batch<<<dotv_blocks, 256, 0, s_build>>>(dvb);
    cudaEventRecord(ev_join2, s_build);

    k_gemm_batch<<<gemm2_blocks, 256>>>(gb2);
    cudaStreamWaitEvent(0, ev_join2, 0);

    // Layer 2 edge phase
    k_segw_batch<<<sw2_blocks, 256>>>(sw2, val, w);
    k_gat_batch<<<gw3_blocks, 256>>>(gw3, val, w);
    k_gat_batch<<<gw4_blocks, 256>>>(gw4, val, w);
}